// round 4
// baseline (speedup 1.0000x reference)
#include <cuda_runtime.h>
#include <math.h>

// Problem constants: B=64, Lq=Lk=1024, D=64
#define BDIM   64
#define LDIM   1024
#define DDIM   64
#define TQ     16          // q rows per CTA
#define KT     512         // k/v rows per smem tile
#define NTHR   512
#define SROW   1028        // scores smem row stride (floats)
#define KROW   68          // k/v smem row stride (floats)

// smem floats: q_s[16*68] | kv_s[512*68] | sc_s[16*1028]  = 52352 floats (~209.4 KB)
#define SMEM_FLOATS (TQ*KROW + KT*KROW + TQ*SROW)

__global__ __launch_bounds__(NTHR, 1)
void sparse_attn_kernel(const float* __restrict__ qg_,
                        const float* __restrict__ kg_,
                        const float* __restrict__ vg_,
                        const int* __restrict__ maskg,
                        float* __restrict__ outg,
                        float* __restrict__ attng)
{
    extern __shared__ float smem[];
    float* q_s  = smem;                       // 16 x 68
    float* kv_s = q_s + TQ * KROW;            // 512 x 68
    float* sc_s = kv_s + KT * KROW;           // 16 x 1028

    const int qt  = blockIdx.x;               // 0..63
    const int b   = blockIdx.y;               // 0..63
    const int tid = threadIdx.x;

    const int q_row0 = qt * TQ;
    const float* qg = qg_ + ((size_t)b * LDIM + q_row0) * DDIM;
    const float* kg = kg_ + (size_t)b * LDIM * DDIM;
    const float* vg = vg_ + (size_t)b * LDIM * DDIM;

    // ---- load q tile (16x64), pre-scaled by 1/8; 256 float4 by threads <256 ----
    if (tid < 256) {
        const int r  = tid >> 4;
        const int c4 = (tid & 15) * 4;
        float4 t = *(const float4*)(qg + r * DDIM + c4);
        float* dst = q_s + r * KROW + c4;
        dst[0] = t.x * 0.125f; dst[1] = t.y * 0.125f;
        dst[2] = t.z * 0.125f; dst[3] = t.w * 0.125f;
    }

    // ==================== GEMM1: scores = (q/8) . k^T ====================
    const int ty = tid >> 7;    // 0..3 -> rows ty*4+r
    const int tx = tid & 127;   // 0..127 -> cols tx + 128*c
    for (int kt = 0; kt < LDIM / KT; kt++) {
        __syncthreads();
        // stage k tile [512 x 64]
        #pragma unroll
        for (int i = 0; i < 16; i++) {
            int f   = i * NTHR + tid;
            int row = f >> 4;
            int c4  = (f & 15) * 4;
            *(float4*)(kv_s + row * KROW + c4) =
                *(const float4*)(kg + (size_t)(kt * KT + row) * DDIM + c4);
        }
        __syncthreads();

        float acc[4][4] = {};
        #pragma unroll
        for (int d = 0; d < DDIM; d += 4) {
            float4 qv[4], kv[4];
            #pragma unroll
            for (int r = 0; r < 4; r++) qv[r] = *(float4*)(q_s + (ty * 4 + r) * KROW + d);
            #pragma unroll
            for (int c = 0; c < 4; c++) kv[c] = *(float4*)(kv_s + (tx + 128 * c) * KROW + d);
            #pragma unroll
            for (int r = 0; r < 4; r++)
                #pragma unroll
                for (int c = 0; c < 4; c++)
                    acc[r][c] += qv[r].x * kv[c].x + qv[r].y * kv[c].y
                               + qv[r].z * kv[c].z + qv[r].w * kv[c].w;
        }
        #pragma unroll
        for (int r = 0; r < 4; r++)
            #pragma unroll
            for (int c = 0; c < 4; c++)
                sc_s[(ty * 4 + r) * SROW + kt * KT + tx + 128 * c] = acc[r][c];
    }
    __syncthreads();

    // ============ mask + sparsemax (Michelot, exact; 1 warp = 1 row) ============
    const int row  = tid >> 5;   // 0..15 (warp id)
    const int sub  = tid & 31;   // lane
    const int grow = q_row0 + row;

    float z[32];
    {
        const int4* m4 = (const int4*)(maskg + ((size_t)b * LDIM + grow) * LDIM);
        #pragma unroll
        for (int jj = 0; jj < 8; jj++) {
            int col = sub * 4 + 128 * jj;
            int4   mb = m4[col >> 2];
            float4 s  = *(float4*)(sc_s + row * SROW + col);
            z[jj * 4 + 0] = mb.x ? -INFINITY : s.x;
            z[jj * 4 + 1] = mb.y ? -INFINITY : s.y;
            z[jj * 4 + 2] = mb.z ? -INFINITY : s.z;
            z[jj * 4 + 3] = mb.w ? -INFINITY : s.w;
        }
    }

    float tau;
    {
        float s = 0.0f; int c = 0;
        #pragma unroll
        for (int i = 0; i < 32; i++)
            if (z[i] > -INFINITY) { s += z[i]; c++; }
        #pragma unroll
        for (int o = 16; o >= 1; o >>= 1) {
            s += __shfl_xor_sync(0xffffffffu, s, o);
            c += __shfl_xor_sync(0xffffffffu, c, o);
        }
        tau = (c > 0) ? (s - 1.0f) / (float)c : INFINITY;
        int prev = c;
        for (int it = 0; it < 64; it++) {
            float s2 = 0.0f; int c2 = 0;
            #pragma unroll
            for (int i = 0; i < 32; i++)
                if (z[i] > tau) { s2 += z[i]; c2++; }
            #pragma unroll
            for (int o = 16; o >= 1; o >>= 1) {
                s2 += __shfl_xor_sync(0xffffffffu, s2, o);
                c2 += __shfl_xor_sync(0xffffffffu, c2, o);
            }
            bool done = (c2 == prev) || (c2 == 0);
            prev = c2;
            if (c2 > 0) tau = (s2 - 1.0f) / (float)c2;
            if (done) break;   // warp-uniform (shuffle-reduced values identical)
        }
    }

    // attn = max(z - tau, 0) -> smem (for GEMM2) + global
    {
        float* attn_row = attng + ((size_t)b * LDIM + grow) * LDIM;
        #pragma unroll
        for (int jj = 0; jj < 8; jj++) {
            int col = sub * 4 + 128 * jj;
            float4 a;
            a.x = fmaxf(z[jj * 4 + 0] - tau, 0.0f);
            a.y = fmaxf(z[jj * 4 + 1] - tau, 0.0f);
            a.z = fmaxf(z[jj * 4 + 2] - tau, 0.0f);
            a.w = fmaxf(z[jj * 4 + 3] - tau, 0.0f);
            *(float4*)(sc_s + row * SROW + col) = a;
            *(float4*)(attn_row + col) = a;
        }
    }

    // ==================== GEMM2: out = attn . v ====================
    const int w    = tid >> 5;         // warp 0..15 -> j-slice
    const int lane = tid & 31;
    const int rp   = lane & 7;         // rows rp, rp+8
    const int cg   = lane >> 3;        // col group base cg*16
    float4 acc0[4] = {}, acc1[4] = {};

    for (int ch = 0; ch < 2; ch++) {
        __syncthreads();   // protects sc_s (first iter) and kv_s reuse
        // stage v chunk [512 x 64]
        #pragma unroll
        for (int i = 0; i < 16; i++) {
            int f   = i * NTHR + tid;
            int r   = f >> 4;
            int c4  = (f & 15) * 4;
            *(float4*)(kv_s + r * KROW + c4) =
                *(const float4*)(vg + (size_t)(ch * KT + r) * DDIM + c4);
        }
        __syncthreads();

        const int jbase = w * 32;
        #pragma unroll 8
        for (int j = 0; j < 32; j++) {
            int vr = jbase + j;
            float a0 = sc_s[rp * SROW + ch * KT + vr];
            float a1 = sc_s[(rp + 8) * SROW + ch * KT + vr];
            #pragma unroll
            for (int g = 0; g < 4; g++) {
                int gp = (g + cg) & 3;   // bank stagger across cg lanes
                float4 vv = *(float4*)(kv_s + vr * KROW + cg * 16 + gp * 4);
                acc0[gp].x += a0 * vv.x; acc0[gp].y += a0 * vv.y;
                acc0[gp].z += a0 * vv.z; acc0[gp].w += a0 * vv.w;
                acc1[gp].x += a1 * vv.x; acc1[gp].y += a1 * vv.y;
                acc1[gp].z += a1 * vv.z; acc1[gp].w += a1 * vv.w;
            }
        }
    }
    __syncthreads();

    // cross-warp reduction: 16 warps x (16x64) partials through sc_s
    float* red = sc_s;   // 16 * 1024 floats = 16384 <= 16*1028
    #pragma unroll
    for (int g = 0; g < 4; g++) {
        int gp = (g + cg) & 3;   // same stagger on stores
        *(float4*)(red + w * 1024 + rp * 64 + cg * 16 + gp * 4)       = acc0[gp];
        *(float4*)(red + w * 1024 + (rp + 8) * 64 + cg * 16 + gp * 4) = acc1[gp];
    }
    __syncthreads();
    if (tid < 256) {
        int o = tid * 4;            // 0..1020
        float4 sum = make_float4(0.f, 0.f, 0.f, 0.f);
        #pragma unroll
        for (int w2 = 0; w2 < 16; w2++) {
            float4 p = *(float4*)(red + w2 * 1024 + o);
            sum.x += p.x; sum.y += p.y; sum.z += p.z; sum.w += p.w;
        }
        int r = o >> 6, c = o & 63;
        *(float4*)(outg + ((size_t)b * LDIM + q_row0 + r) * DDIM + c) = sum;
    }
}

extern "C" void kernel_launch(void* const* d_in, const int* in_sizes, int n_in,
                              void* d_out, int out_size)
{
    const float* q    = (const float*)d_in[0];
    const float* k    = (const float*)d_in[1];
    const float* v    = (const float*)d_in[2];
    const int*   mask = (const int*)d_in[3];

    float* out  = (float*)d_out;                                // [B, Lq, D]
    float* attn = (float*)d_out + (size_t)BDIM * LDIM * DDIM;   // [B, Lq, Lk]

    const size_t smem_bytes = SMEM_FLOATS * sizeof(float);      // ~209.4 KB
    cudaFuncSetAttribute(sparse_attn_kernel,
                         cudaFuncAttributeMaxDynamicSharedMemorySize,
                         (int)smem_bytes);

    dim3 grid(LDIM / TQ, BDIM);   // (64, 64)
    dim3 block(NTHR);
    sparse_attn_kernel<<<grid, block, smem_bytes>>>(q, k, v, mask, out, attn);
}

// round 7
// speedup vs baseline: 6.7601x; 6.7601x over previous
#include <cuda_runtime.h>
#include <math.h>

// Problem constants: B=64, Lq=Lk=1024, D=64
#define BDIM   64
#define LDIM   1024
#define DDIM   64
#define TQ     16          // q rows per CTA
#define KT     512         // k/v rows per smem tile
#define NTHR   512
#define SROW   1028        // scores smem row stride (floats)
#define KROW   68          // k/v smem row stride (floats)

// smem floats: q_s[16*68] | kv_s[512*68] | sc_s[16*1028]  = 52352 floats (~209.4 KB)
#define SMEM_FLOATS (TQ*KROW + KT*KROW + TQ*SROW)

__global__ __launch_bounds__(NTHR, 1)
void sparse_attn_kernel(const float* __restrict__ qg_,
                        const float* __restrict__ kg_,
                        const float* __restrict__ vg_,
                        const int* __restrict__ maskg,
                        float* __restrict__ outg,
                        float* __restrict__ attng)
{
    extern __shared__ float smem[];
    float* q_s  = smem;                       // 16 x 68
    float* kv_s = q_s + TQ * KROW;            // 512 x 68
    float* sc_s = kv_s + KT * KROW;           // 16 x 1028

    const int qt  = blockIdx.x;               // 0..63
    const int b   = blockIdx.y;               // 0..63
    const int tid = threadIdx.x;

    const int q_row0 = qt * TQ;
    const float* qg = qg_ + ((size_t)b * LDIM + q_row0) * DDIM;
    const float* kg = kg_ + (size_t)b * LDIM * DDIM;
    const float* vg = vg_ + (size_t)b * LDIM * DDIM;

    // ---- load q tile (16x64), pre-scaled by 1/8 ----
    if (tid < 256) {
        const int r  = tid >> 4;
        const int c4 = (tid & 15) * 4;
        float4 t = *(const float4*)(qg + r * DDIM + c4);
        float* dst = q_s + r * KROW + c4;
        dst[0] = t.x * 0.125f; dst[1] = t.y * 0.125f;
        dst[2] = t.z * 0.125f; dst[3] = t.w * 0.125f;
    }

    // ==================== GEMM1: scores = (q/8) . k^T ====================
    const int ty = tid >> 7;    // 0..3 -> rows ty*4+r
    const int tx = tid & 127;   // 0..127 -> cols tx + 128*c
    for (int kt = 0; kt < LDIM / KT; kt++) {
        __syncthreads();
        // stage k tile [512 x 64]
        #pragma unroll
        for (int i = 0; i < 16; i++) {
            int f   = i * NTHR + tid;
            int row = f >> 4;
            int c4  = (f & 15) * 4;
            *(float4*)(kv_s + row * KROW + c4) =
                *(const float4*)(kg + (size_t)(kt * KT + row) * DDIM + c4);
        }
        __syncthreads();

        float acc[4][4] = {};
        #pragma unroll
        for (int d = 0; d < DDIM; d += 4) {
            float4 qv[4], kv[4];
            #pragma unroll
            for (int r = 0; r < 4; r++) qv[r] = *(float4*)(q_s + (ty * 4 + r) * KROW + d);
            #pragma unroll
            for (int c = 0; c < 4; c++) kv[c] = *(float4*)(kv_s + (tx + 128 * c) * KROW + d);
            #pragma unroll
            for (int r = 0; r < 4; r++)
                #pragma unroll
                for (int c = 0; c < 4; c++)
                    acc[r][c] += qv[r].x * kv[c].x + qv[r].y * kv[c].y
                               + qv[r].z * kv[c].z + qv[r].w * kv[c].w;
        }
        #pragma unroll
        for (int r = 0; r < 4; r++)
            #pragma unroll
            for (int c = 0; c < 4; c++)
                sc_s[(ty * 4 + r) * SROW + kt * KT + tx + 128 * c] = acc[r][c];
    }
    __syncthreads();

    // ============ mask + sparsemax (Michelot, exact; 1 warp = 1 row) ============
    const int row  = tid >> 5;   // 0..15 (warp id)
    const int sub  = tid & 31;   // lane
    const int grow = q_row0 + row;

    float z[32];
    {
        const int4* m4 = (const int4*)(maskg + ((size_t)b * LDIM + grow) * LDIM);
        #pragma unroll
        for (int jj = 0; jj < 8; jj++) {
            int col = sub * 4 + 128 * jj;
            int4   mb = m4[col >> 2];
            float4 s  = *(float4*)(sc_s + row * SROW + col);
            z[jj * 4 + 0] = mb.x ? -INFINITY : s.x;
            z[jj * 4 + 1] = mb.y ? -INFINITY : s.y;
            z[jj * 4 + 2] = mb.z ? -INFINITY : s.z;
            z[jj * 4 + 3] = mb.w ? -INFINITY : s.w;
        }
    }

    float tau;
    {
        float s = 0.0f; int c = 0;
        #pragma unroll
        for (int i = 0; i < 32; i++)
            if (z[i] > -INFINITY) { s += z[i]; c++; }
        #pragma unroll
        for (int o = 16; o >= 1; o >>= 1) {
            s += __shfl_xor_sync(0xffffffffu, s, o);
            c += __shfl_xor_sync(0xffffffffu, c, o);
        }
        tau = (c > 0) ? (s - 1.0f) / (float)c : INFINITY;
        int prev = c;
        for (int it = 0; it < 64; it++) {
            float s2 = 0.0f; int c2 = 0;
            #pragma unroll
            for (int i = 0; i < 32; i++)
                if (z[i] > tau) { s2 += z[i]; c2++; }
            #pragma unroll
            for (int o = 16; o >= 1; o >>= 1) {
                s2 += __shfl_xor_sync(0xffffffffu, s2, o);
                c2 += __shfl_xor_sync(0xffffffffu, c2, o);
            }
            bool done = (c2 == prev) || (c2 == 0);
            prev = c2;
            if (c2 > 0) tau = (s2 - 1.0f) / (float)c2;
            if (done) break;   // warp-uniform after shuffle reduction
        }
    }

    // attn = max(z - tau, 0) -> smem (for GEMM2) + global
    {
        float* attn_row = attng + ((size_t)b * LDIM + grow) * LDIM;
        #pragma unroll
        for (int jj = 0; jj < 8; jj++) {
            int col = sub * 4 + 128 * jj;
            float4 a;
            a.x = fmaxf(z[jj * 4 + 0] - tau, 0.0f);
            a.y = fmaxf(z[jj * 4 + 1] - tau, 0.0f);
            a.z = fmaxf(z[jj * 4 + 2] - tau, 0.0f);
            a.w = fmaxf(z[jj * 4 + 3] - tau, 0.0f);
            *(float4*)(sc_s + row * SROW + col) = a;
            *(float4*)(attn_row + col) = a;
        }
    }

    // ==================== GEMM2: out = attn . v ====================
    // acc0[g]/acc1[g] (COMPILE-TIME index) hold the partial for column
    // cg*16 + ((g+cg)&3)*4 — the stagger lives only in the ADDRESS, so
    // per-instruction banks are disjoint across cg groups AND registers
    // never get dynamically indexed (no local-memory spill).
    const int w    = tid >> 5;         // warp 0..15 -> j-slice
    const int lane = tid & 31;
    const int rp   = lane & 7;         // rows rp, rp+8
    const int cg   = lane >> 3;        // col group base cg*16
    float4 acc0[4] = {}, acc1[4] = {};

    for (int ch = 0; ch < 2; ch++) {
        __syncthreads();   // protects sc_s (first iter) and kv_s reuse
        // stage v chunk [512 x 64]
        #pragma unroll
        for (int i = 0; i < 16; i++) {
            int f   = i * NTHR + tid;
            int r   = f >> 4;
            int c4  = (f & 15) * 4;
            *(float4*)(kv_s + r * KROW + c4) =
                *(const float4*)(vg + (size_t)(ch * KT + r) * DDIM + c4);
        }
        __syncthreads();

        const int jbase = w * 32;
        #pragma unroll 8
        for (int j = 0; j < 32; j++) {
            int vr = jbase + j;
            float a0 = sc_s[rp * SROW + ch * KT + vr];
            float a1 = sc_s[(rp + 8) * SROW + ch * KT + vr];
            const float* vrow = kv_s + vr * KROW + cg * 16;
            #pragma unroll
            for (int g = 0; g < 4; g++) {
                float4 vv = *(const float4*)(vrow + (((g + cg) & 3) * 4));
                acc0[g].x += a0 * vv.x; acc0[g].y += a0 * vv.y;
                acc0[g].z += a0 * vv.z; acc0[g].w += a0 * vv.w;
                acc1[g].x += a1 * vv.x; acc1[g].y += a1 * vv.y;
                acc1[g].z += a1 * vv.z; acc1[g].w += a1 * vv.w;
            }
        }
    }
    __syncthreads();

    // cross-warp reduction: 16 warps x (16x64) partials through sc_s.
    // Store applies the same address permutation so data lands at its
    // true column; acc index stays compile-time.
    float* red = sc_s;   // 16 * 1024 floats <= 16*1028
    #pragma unroll
    for (int g = 0; g < 4; g++) {
        int colo = cg * 16 + (((g + cg) & 3) * 4);
        *(float4*)(red + w * 1024 + rp * 64 + colo)       = acc0[g];
        *(float4*)(red + w * 1024 + (rp + 8) * 64 + colo) = acc1[g];
    }
    __syncthreads();
    if (tid < 256) {
        int o = tid * 4;            // 0..1020
        float4 sum = make_float4(0.f, 0.f, 0.f, 0.f);
        #pragma unroll
        for (int w2 = 0; w2 < 16; w2++) {
            float4 p = *(float4*)(red + w2 * 1024 + o);
            sum.x += p.x; sum.y += p.y; sum.z += p.z; sum.w += p.w;
        }
        int r = o >> 6, c = o & 63;
        *(float4*)(outg + ((size_t)b * LDIM + q_row0 + r) * DDIM + c) = sum;
    }
}

extern "C" void kernel_launch(void* const* d_in, const int* in_sizes, int n_in,
                              void* d_out, int out_size)
{
    const float* q    = (const float*)d_in[0];
    const float* k    = (const float*)d_in[1];
    const float* v    = (const float*)d_in[2];
    const int*   mask = (const int*)d_in[3];

    float* out  = (float*)d_out;                                // [B, Lq, D]
    float* attn = (float*)d_out + (size_t)BDIM * LDIM * DDIM;   // [B, Lq, Lk]

    const size_t smem_bytes = SMEM_FLOATS * sizeof(float);      // ~209.4 KB
    cudaFuncSetAttribute(sparse_attn_kernel,
                         cudaFuncAttributeMaxDynamicSharedMemorySize,
                         (int)smem_bytes);

    dim3 grid(LDIM / TQ, BDIM);   // (64, 64)
    dim3 block(NTHR);
    sparse_attn_kernel<<<grid, block, smem_bytes>>>(q, k, v, mask, out, attn);
}

// round 8
// speedup vs baseline: 7.8691x; 1.1640x over previous
#include <cuda_runtime.h>
#include <math.h>
#include <stdint.h>

// Problem constants: B=64, Lq=Lk=1024, D=64
#define BDIM   64
#define LDIM   1024
#define DDIM   64
#define TQ     16          // q rows per CTA
#define KT     128         // k/v rows per smem tile
#define NTHR   512
#define SROW   1028        // scores smem row stride (floats)
#define KROW   68          // k/v smem row stride (floats)

// smem floats: q_hi[16*68] | q_lo[16*68] | kv_s[128*68] | sc_s[16*1028]
#define SMEM_FLOATS (2*TQ*KROW + KT*KROW + TQ*SROW)   // 27328 floats = 109.3 KB

// ---- tf32 helpers ----
__device__ __forceinline__ uint32_t f2tf32(float x) {
    uint32_t r;
    asm("cvt.rna.tf32.f32 %0, %1;" : "=r"(r) : "f"(x));
    return r;
}
__device__ __forceinline__ void split_tf32(float x, uint32_t& hi, uint32_t& lo) {
    asm("cvt.rna.tf32.f32 %0, %1;" : "=r"(hi) : "f"(x));
    float rem = x - __uint_as_float(hi);
    asm("cvt.rna.tf32.f32 %0, %1;" : "=r"(lo) : "f"(rem));
}
#define MMA_TF32(c0,c1,c2,c3, a0,a1,a2,a3, b0,b1)                                  \
    asm("mma.sync.aligned.m16n8k8.row.col.f32.tf32.tf32.f32 "                      \
        "{%0,%1,%2,%3}, {%4,%5,%6,%7}, {%8,%9}, {%0,%1,%2,%3};"                    \
        : "+f"(c0), "+f"(c1), "+f"(c2), "+f"(c3)                                   \
        : "r"(a0), "r"(a1), "r"(a2), "r"(a3), "r"(b0), "r"(b1))

__global__ __launch_bounds__(NTHR, 2)
void sparse_attn_kernel(const float* __restrict__ qg_,
                        const float* __restrict__ kg_,
                        const float* __restrict__ vg_,
                        const int* __restrict__ maskg,
                        float* __restrict__ outg,
                        float* __restrict__ attng)
{
    extern __shared__ float smem[];
    float* q_hi = smem;                        // 16 x 68 (tf32-hi of q/8)
    float* q_lo = q_hi + TQ * KROW;            // 16 x 68 (tf32-lo of q/8)
    float* kv_s = q_lo + TQ * KROW;            // 128 x 68
    float* sc_s = kv_s + KT * KROW;            // 16 x 1028

    const int qt  = blockIdx.x;                // 0..63
    const int b   = blockIdx.y;                // 0..63
    const int tid = threadIdx.x;
    const int w    = tid >> 5;                 // warp 0..15
    const int lane = tid & 31;
    const int gr   = lane >> 2;                // groupID 0..7
    const int tg   = lane & 3;                 // threadID_in_group 0..3

    const int q_row0 = qt * TQ;
    const float* qg = qg_ + ((size_t)b * LDIM + q_row0) * DDIM;
    const float* kg = kg_ + (size_t)b * LDIM * DDIM;
    const float* vg = vg_ + (size_t)b * LDIM * DDIM;

    // ---- load q tile (16x64), scale by 1/8, split into tf32 hi/lo planes ----
    if (tid < 256) {
        const int r  = tid >> 4;
        const int c4 = (tid & 15) * 4;
        float4 t = *(const float4*)(qg + r * DDIM + c4);
        float xs[4] = { t.x * 0.125f, t.y * 0.125f, t.z * 0.125f, t.w * 0.125f };
        #pragma unroll
        for (int j = 0; j < 4; j++) {
            uint32_t hi, lo;
            split_tf32(xs[j], hi, lo);
            q_hi[r * KROW + c4 + j] = __uint_as_float(hi);
            q_lo[r * KROW + c4 + j] = __uint_as_float(lo);
        }
    }

    // ==================== GEMM1: scores = (q/8) . k^T  (3xTF32 mma) ====================
    // tile t: k rows [t*128, t*128+128) = C cols; warp w owns cols [t*128+8w, +8)
    for (int t = 0; t < LDIM / KT; t++) {
        __syncthreads();
        #pragma unroll
        for (int i = 0; i < 4; i++) {          // stage k tile [128 x 64]
            int f   = i * NTHR + tid;
            int row = f >> 4;
            int c4  = (f & 15) * 4;
            *(float4*)(kv_s + row * KROW + c4) =
                *(const float4*)(kg + (size_t)(t * KT + row) * DDIM + c4);
        }
        __syncthreads();

        float c0 = 0.f, c1 = 0.f, c2 = 0.f, c3 = 0.f;
        const int nb = 8 * w;                  // local col base in tile
        #pragma unroll
        for (int kc = 0; kc < DDIM; kc += 8) {
            // A fragments (q) from pre-split planes
            uint32_t a0h = __float_as_uint(q_hi[gr * KROW + kc + tg]);
            uint32_t a1h = __float_as_uint(q_hi[(gr + 8) * KROW + kc + tg]);
            uint32_t a2h = __float_as_uint(q_hi[gr * KROW + kc + tg + 4]);
            uint32_t a3h = __float_as_uint(q_hi[(gr + 8) * KROW + kc + tg + 4]);
            uint32_t a0l = __float_as_uint(q_lo[gr * KROW + kc + tg]);
            uint32_t a1l = __float_as_uint(q_lo[(gr + 8) * KROW + kc + tg]);
            uint32_t a2l = __float_as_uint(q_lo[gr * KROW + kc + tg + 4]);
            uint32_t a3l = __float_as_uint(q_lo[(gr + 8) * KROW + kc + tg + 4]);
            // B fragments (k): B[k=d][n=col] = k_s[col][d]
            float b0f = kv_s[(nb + gr) * KROW + kc + tg];
            float b1f = kv_s[(nb + gr) * KROW + kc + tg + 4];
            uint32_t b0h, b0l, b1h, b1l;
            split_tf32(b0f, b0h, b0l);
            split_tf32(b1f, b1h, b1l);
            MMA_TF32(c0, c1, c2, c3, a0h, a1h, a2h, a3h, b0l, b1l);
            MMA_TF32(c0, c1, c2, c3, a0l, a1l, a2l, a3l, b0h, b1h);
            MMA_TF32(c0, c1, c2, c3, a0h, a1h, a2h, a3h, b0h, b1h);
        }
        const int col0 = t * KT + nb;
        *(float2*)(sc_s + gr * SROW + col0 + 2 * tg)       = make_float2(c0, c1);
        *(float2*)(sc_s + (gr + 8) * SROW + col0 + 2 * tg) = make_float2(c2, c3);
    }
    __syncthreads();

    // ============ mask + sparsemax (Michelot, exact; 1 warp = 1 row) ============
    const int row  = w;          // 0..15
    const int sub  = lane;
    const int grow = q_row0 + row;

    float z[32];
    {
        const int4* m4 = (const int4*)(maskg + ((size_t)b * LDIM + grow) * LDIM);
        #pragma unroll
        for (int jj = 0; jj < 8; jj++) {
            int col = sub * 4 + 128 * jj;
            int4   mb = m4[col >> 2];
            float4 s  = *(float4*)(sc_s + row * SROW + col);
            z[jj * 4 + 0] = mb.x ? -INFINITY : s.x;
            z[jj * 4 + 1] = mb.y ? -INFINITY : s.y;
            z[jj * 4 + 2] = mb.z ? -INFINITY : s.z;
            z[jj * 4 + 3] = mb.w ? -INFINITY : s.w;
        }
    }

    float tau;
    {
        float s = 0.0f; int c = 0;
        #pragma unroll
        for (int i = 0; i < 32; i++)
            if (z[i] > -INFINITY) { s += z[i]; c++; }
        #pragma unroll
        for (int o = 16; o >= 1; o >>= 1) {
            s += __shfl_xor_sync(0xffffffffu, s, o);
            c += __shfl_xor_sync(0xffffffffu, c, o);
        }
        tau = (c > 0) ? (s - 1.0f) / (float)c : INFINITY;
        int prev = c;
        for (int it = 0; it < 64; it++) {
            float s2 = 0.0f; int c2 = 0;
            #pragma unroll
            for (int i = 0; i < 32; i++)
                if (z[i] > tau) { s2 += z[i]; c2++; }
            #pragma unroll
            for (int o = 16; o >= 1; o >>= 1) {
                s2 += __shfl_xor_sync(0xffffffffu, s2, o);
                c2 += __shfl_xor_sync(0xffffffffu, c2, o);
            }
            bool done = (c2 == prev) || (c2 == 0);
            prev = c2;
            if (c2 > 0) tau = (s2 - 1.0f) / (float)c2;
            if (done) break;   // warp-uniform after shuffle reduction
        }
    }

    // attn = max(z - tau, 0) -> smem (for GEMM2) + global
    {
        float* attn_row = attng + ((size_t)b * LDIM + grow) * LDIM;
        #pragma unroll
        for (int jj = 0; jj < 8; jj++) {
            int col = sub * 4 + 128 * jj;
            float4 a;
            a.x = fmaxf(z[jj * 4 + 0] - tau, 0.0f);
            a.y = fmaxf(z[jj * 4 + 1] - tau, 0.0f);
            a.z = fmaxf(z[jj * 4 + 2] - tau, 0.0f);
            a.w = fmaxf(z[jj * 4 + 3] - tau, 0.0f);
            *(float4*)(sc_s + row * SROW + col) = a;
            *(float4*)(attn_row + col) = a;
        }
    }

    // ==================== GEMM2: out = attn . v  (3xTF32 mma) ====================
    // tile t: v rows [t*128, +128); warp w handles k-chunk [t*128+8w, +8), all 8 n-tiles
    float d0[8], d1[8], d2[8], d3[8];
    #pragma unroll
    for (int nt = 0; nt < 8; nt++) { d0[nt] = d1[nt] = d2[nt] = d3[nt] = 0.f; }

    for (int t = 0; t < LDIM / KT; t++) {
        __syncthreads();   // t=0 also orders attn STS (sc_s) before cross-warp reads
        #pragma unroll
        for (int i = 0; i < 4; i++) {          // stage v tile [128 x 64]
            int f   = i * NTHR + tid;
            int r   = f >> 4;
            int c4  = (f & 15) * 4;
            *(float4*)(kv_s + r * KROW + c4) =
                *(const float4*)(vg + (size_t)(t * KT + r) * DDIM + c4);
        }
        __syncthreads();

        const int kb = t * KT + 8 * w;         // global k base for this warp
        const int lb = 8 * w;                  // local v row base
        // A fragments (attn, fp32 in sc_s) -> split
        uint32_t a0h, a0l, a1h, a1l, a2h, a2l, a3h, a3l;
        split_tf32(sc_s[gr * SROW + kb + tg],           a0h, a0l);
        split_tf32(sc_s[(gr + 8) * SROW + kb + tg],     a1h, a1l);
        split_tf32(sc_s[gr * SROW + kb + tg + 4],       a2h, a2l);
        split_tf32(sc_s[(gr + 8) * SROW + kb + tg + 4], a3h, a3l);

        #pragma unroll
        for (int nt = 0; nt < 8; nt++) {
            float b0f = kv_s[(lb + tg) * KROW + nt * 8 + gr];
            float b1f = kv_s[(lb + tg + 4) * KROW + nt * 8 + gr];
            uint32_t b0h, b0l, b1h, b1l;
            split_tf32(b0f, b0h, b0l);
            split_tf32(b1f, b1h, b1l);
            MMA_TF32(d0[nt], d1[nt], d2[nt], d3[nt], a0h, a1h, a2h, a3h, b0l, b1l);
            MMA_TF32(d0[nt], d1[nt], d2[nt], d3[nt], a0l, a1l, a2l, a3l, b0h, b1h);
            MMA_TF32(d0[nt], d1[nt], d2[nt], d3[nt], a0h, a1h, a2h, a3h, b0h, b1h);
        }
    }
    __syncthreads();   // all warps done reading attn from sc_s

    // cross-warp reduction: 16 partial (16x64) tiles through sc_s
    float* red = sc_s;   // 16*1024 floats <= 16*1028
    #pragma unroll
    for (int nt = 0; nt < 8; nt++) {
        *(float2*)(red + w * 1024 + gr * 64 + nt * 8 + 2 * tg)       = make_float2(d0[nt], d1[nt]);
        *(float2*)(red + w * 1024 + (gr + 8) * 64 + nt * 8 + 2 * tg) = make_float2(d2[nt], d3[nt]);
    }
    __syncthreads();
    if (tid < 256) {
        int o = tid * 4;            // 0..1020
        float4 sum = make_float4(0.f, 0.f, 0.f, 0.f);
        #pragma unroll
        for (int w2 = 0; w2 < 16; w2++) {
            float4 p = *(float4*)(red + w2 * 1024 + o);
            sum.x += p.x; sum.y += p.y; sum.z += p.z; sum.w += p.w;
        }
        int r = o >> 6, c = o & 63;
        *(float4*)(outg + ((size_t)b * LDIM + q_row0 + r) * DDIM + c) = sum;
    }
}

extern "C" void kernel_launch(void* const* d_in, const int* in_sizes, int n_in,
                              void* d_out, int out_size)
{
    const float* q    = (const float*)d_in[0];
    const float* k    = (const float*)d_in[1];
    const float* v    = (const float*)d_in[2];
    const int*   mask = (const int*)d_in[3];

    float* out  = (float*)d_out;                                // [B, Lq, D]
    float* attn = (float*)d_out + (size_t)BDIM * LDIM * DDIM;   // [B, Lq, Lk]

    const size_t smem_bytes = SMEM_FLOATS * sizeof(float);      // ~109.3 KB
    cudaFuncSetAttribute(sparse_attn_kernel,
                         cudaFuncAttributeMaxDynamicSharedMemorySize,
                         (int)smem_bytes);

    dim3 grid(LDIM / TQ, BDIM);   // (64, 64)
    dim3 block(NTHR);
    sparse_attn_kernel<<<grid, block, smem_bytes>>>(q, k, v, mask, out, attn);
}

// round 9
// speedup vs baseline: 8.6329x; 1.0971x over previous
#include <cuda_runtime.h>
#include <cuda_bf16.h>
#include <math.h>
#include <stdint.h>

// Problem constants: B=64, Lq=Lk=1024, D=64
#define BDIM   64
#define LDIM   1024
#define DDIM   64
#define TQ     16          // q rows per CTA
#define KT     128         // k/v rows per smem tile
#define NTHR   512
#define SCROW  1036        // fp32 score smem stride (floats)
#define APROW  1032        // attn bf16 plane stride (bf16 elems)
#define KPROW  72          // k/v bf16 plane stride (bf16 elems) -> 144B rows
#define QPROW  72

// smem byte layout:
//  [0)      q_hi 16x72 bf16 (2304) | q_lo (2304)                  -> 4608
//  [4608)   k_hi 128x72 bf16 (18432) | k_lo (18432)  (v reuses;   -> 36864
//           GEMM2 reduction scratch 32KB also aliases here)
//  [41472)  sc fp32 16x1036 (66304)  (attn bf16 hi/lo planes alias:
//           2 x 16x1032x2 = 66048 <= 66304)
#define OFF_QHI 0
#define OFF_QLO 2304
#define OFF_KHI 4608
#define OFF_KLO 23040
#define OFF_SC  41472
#define SMEM_BYTES 107776

__device__ __forceinline__ uint32_t sptr(const void* p) {
    return (uint32_t)__cvta_generic_to_shared(p);
}
__device__ __forceinline__ void bsplit(float x, uint16_t& h, uint16_t& l) {
    __nv_bfloat16 bh = __float2bfloat16(x);
    float r = x - __bfloat162float(bh);
    __nv_bfloat16 bl = __float2bfloat16(r);
    h = __bfloat16_as_ushort(bh);
    l = __bfloat16_as_ushort(bl);
}

#define LDSM_X4(r0,r1,r2,r3, a)                                                  \
    asm volatile("ldmatrix.sync.aligned.m8n8.x4.shared.b16 {%0,%1,%2,%3}, [%4];" \
        : "=r"(r0), "=r"(r1), "=r"(r2), "=r"(r3) : "r"(a))
#define LDSM_X2(r0,r1, a)                                                        \
    asm volatile("ldmatrix.sync.aligned.m8n8.x2.shared.b16 {%0,%1}, [%2];"       \
        : "=r"(r0), "=r"(r1) : "r"(a))
#define LDSM_X2T(r0,r1, a)                                                       \
    asm volatile("ldmatrix.sync.aligned.m8n8.x2.trans.shared.b16 {%0,%1}, [%2];" \
        : "=r"(r0), "=r"(r1) : "r"(a))
#define MMA_BF16(c0,c1,c2,c3, a0,a1,a2,a3, b0,b1)                                \
    asm volatile("mma.sync.aligned.m16n8k16.row.col.f32.bf16.bf16.f32 "          \
        "{%0,%1,%2,%3}, {%4,%5,%6,%7}, {%8,%9}, {%0,%1,%2,%3};"                  \
        : "+f"(c0), "+f"(c1), "+f"(c2), "+f"(c3)                                 \
        : "r"(a0), "r"(a1), "r"(a2), "r"(a3), "r"(b0), "r"(b1))

__global__ __launch_bounds__(NTHR, 2)
void sparse_attn_kernel(const float* __restrict__ qg_,
                        const float* __restrict__ kg_,
                        const float* __restrict__ vg_,
                        const int* __restrict__ maskg,
                        float* __restrict__ outg,
                        float* __restrict__ attng)
{
    extern __shared__ char smem[];
    uint16_t* q_hi = (uint16_t*)(smem + OFF_QHI);
    uint16_t* q_lo = (uint16_t*)(smem + OFF_QLO);
    uint16_t* k_hi = (uint16_t*)(smem + OFF_KHI);   // also v planes; also red scratch
    uint16_t* k_lo = (uint16_t*)(smem + OFF_KLO);
    float*    sc_s = (float*)   (smem + OFF_SC);
    uint16_t* a_hi = (uint16_t*)(smem + OFF_SC);              // attn hi plane (aliases sc)
    uint16_t* a_lo = a_hi + TQ * APROW;                       // attn lo plane

    const int qt   = blockIdx.x;            // 0..63
    const int b    = blockIdx.y;            // 0..63
    const int tid  = threadIdx.x;
    const int w    = tid >> 5;              // warp 0..15
    const int lane = tid & 31;
    const int gr   = lane >> 2;             // 0..7
    const int tg   = lane & 3;              // 0..3

    const int q_row0 = qt * TQ;
    const float* qg = qg_ + ((size_t)b * LDIM + q_row0) * DDIM;
    const float* kg = kg_ + (size_t)b * LDIM * DDIM;
    const float* vg = vg_ + (size_t)b * LDIM * DDIM;

    // ldmatrix lane addressing (shared by all x4/x2 uses)
    const int g4      = lane >> 3;                        // matrix id 0..3
    const int arow    = (lane & 7) | ((g4 & 1) << 3);     // A: row within 16
    const int acolofs = (g4 >> 1) << 3;                   // A: +0 / +8 k-offset
    const int li      = lane & 15;
    const int brow8   = li & 7;                           // B: row within 8
    const int bmat    = li >> 3;                          // B: matrix 0/1

    // ---- stage q tile (16x64), scale 1/8, split -> bf16 hi/lo planes ----
    if (tid < 64) {
        const int r  = tid >> 2;
        const int cs = (tid & 3) * 16;
        const float* src = qg + r * DDIM + cs;
        uint32_t hp[8], lp[8];
        #pragma unroll
        for (int i = 0; i < 4; i++) {
            float4 f = *(const float4*)(src + i * 4);
            uint16_t h0,l0,h1,l1,h2,l2,h3,l3;
            bsplit(f.x * 0.125f, h0, l0); bsplit(f.y * 0.125f, h1, l1);
            bsplit(f.z * 0.125f, h2, l2); bsplit(f.w * 0.125f, h3, l3);
            hp[i*2]   = (uint32_t)h0 | ((uint32_t)h1 << 16);
            hp[i*2+1] = (uint32_t)h2 | ((uint32_t)h3 << 16);
            lp[i*2]   = (uint32_t)l0 | ((uint32_t)l1 << 16);
            lp[i*2+1] = (uint32_t)l2 | ((uint32_t)l3 << 16);
        }
        uint32_t* dh = (uint32_t*)(q_hi + r * QPROW + cs);
        uint32_t* dl = (uint32_t*)(q_lo + r * QPROW + cs);
        *(uint4*)(dh)     = make_uint4(hp[0],hp[1],hp[2],hp[3]);
        *(uint4*)(dh + 4) = make_uint4(hp[4],hp[5],hp[6],hp[7]);
        *(uint4*)(dl)     = make_uint4(lp[0],lp[1],lp[2],lp[3]);
        *(uint4*)(dl + 4) = make_uint4(lp[4],lp[5],lp[6],lp[7]);
    }

    const uint32_t qhi_b = sptr(q_hi), qlo_b = sptr(q_lo);
    const uint32_t khi_b = sptr(k_hi), klo_b = sptr(k_lo);

    // ==================== GEMM1: scores = (q/8) . k^T  (bf16x3 mma) ====================
    const int nb = 8 * w;   // this warp's 8 score-cols within the tile
    for (int t = 0; t < LDIM / KT; t++) {
        __syncthreads();
        // stage k tile [128 x 64] -> bf16 hi/lo planes (each thread: 1 row-quarter)
        {
            const int r  = tid >> 2;
            const int cs = (tid & 3) * 16;
            const float* src = kg + (size_t)(t * KT + r) * DDIM + cs;
            uint32_t hp[8], lp[8];
            #pragma unroll
            for (int i = 0; i < 4; i++) {
                float4 f = *(const float4*)(src + i * 4);
                uint16_t h0,l0,h1,l1,h2,l2,h3,l3;
                bsplit(f.x, h0, l0); bsplit(f.y, h1, l1);
                bsplit(f.z, h2, l2); bsplit(f.w, h3, l3);
                hp[i*2]   = (uint32_t)h0 | ((uint32_t)h1 << 16);
                hp[i*2+1] = (uint32_t)h2 | ((uint32_t)h3 << 16);
                lp[i*2]   = (uint32_t)l0 | ((uint32_t)l1 << 16);
                lp[i*2+1] = (uint32_t)l2 | ((uint32_t)l3 << 16);
            }
            uint32_t* dh = (uint32_t*)(k_hi + r * KPROW + cs);
            uint32_t* dl = (uint32_t*)(k_lo + r * KPROW + cs);
            *(uint4*)(dh)     = make_uint4(hp[0],hp[1],hp[2],hp[3]);
            *(uint4*)(dh + 4) = make_uint4(hp[4],hp[5],hp[6],hp[7]);
            *(uint4*)(dl)     = make_uint4(lp[0],lp[1],lp[2],lp[3]);
            *(uint4*)(dl + 4) = make_uint4(lp[4],lp[5],lp[6],lp[7]);
        }
        __syncthreads();

        float c0 = 0.f, c1 = 0.f, c2 = 0.f, c3 = 0.f;
        #pragma unroll
        for (int kc = 0; kc < DDIM; kc += 16) {
            uint32_t ah0,ah1,ah2,ah3, al0,al1,al2,al3;
            LDSM_X4(ah0,ah1,ah2,ah3, qhi_b + (uint32_t)(arow * QPROW + kc + acolofs) * 2);
            LDSM_X4(al0,al1,al2,al3, qlo_b + (uint32_t)(arow * QPROW + kc + acolofs) * 2);
            uint32_t bh0,bh1, bl0,bl1;
            const uint32_t bofs = (uint32_t)((nb + brow8) * KPROW + kc + bmat * 8) * 2;
            LDSM_X2(bh0,bh1, khi_b + bofs);
            LDSM_X2(bl0,bl1, klo_b + bofs);
            MMA_BF16(c0,c1,c2,c3, ah0,ah1,ah2,ah3, bl0,bl1);  // hi*lo
            MMA_BF16(c0,c1,c2,c3, al0,al1,al2,al3, bh0,bh1);  // lo*hi
            MMA_BF16(c0,c1,c2,c3, ah0,ah1,ah2,ah3, bh0,bh1);  // hi*hi
        }
        float* sp = sc_s + gr * SCROW + t * KT + nb + 2 * tg;
        *(float2*)sp               = make_float2(c0, c1);
        *(float2*)(sp + 8 * SCROW) = make_float2(c2, c3);
    }
    __syncthreads();

    // ============ mask + sparsemax (Michelot, exact; 1 warp = 1 row) ============
    const int row  = w;
    const int sub  = lane;
    const int grow = q_row0 + row;

    float z[32];
    {
        const int4* m4 = (const int4*)(maskg + ((size_t)b * LDIM + grow) * LDIM);
        #pragma unroll
        for (int jj = 0; jj < 8; jj++) {
            int col = sub * 4 + 128 * jj;
            int4   mb = m4[col >> 2];
            float4 s  = *(float4*)(sc_s + row * SCROW + col);
            z[jj*4+0] = mb.x ? -INFINITY : s.x;
            z[jj*4+1] = mb.y ? -INFINITY : s.y;
            z[jj*4+2] = mb.z ? -INFINITY : s.z;
            z[jj*4+3] = mb.w ? -INFINITY : s.w;
        }
    }
    __syncthreads();   // all score reads done before attn planes overwrite sc region

    float tau;
    {
        float s = 0.0f; int c = 0;
        #pragma unroll
        for (int i = 0; i < 32; i++)
            if (z[i] > -INFINITY) { s += z[i]; c++; }
        #pragma unroll
        for (int o = 16; o >= 1; o >>= 1) {
            s += __shfl_xor_sync(0xffffffffu, s, o);
            c += __shfl_xor_sync(0xffffffffu, c, o);
        }
        tau = (c > 0) ? (s - 1.0f) / (float)c : INFINITY;
        int prev = c;
        for (int it = 0; it < 64; it++) {
            float s2 = 0.0f; int c2 = 0;
            #pragma unroll
            for (int i = 0; i < 32; i++)
                if (z[i] > tau) { s2 += z[i]; c2++; }
            #pragma unroll
            for (int o = 16; o >= 1; o >>= 1) {
                s2 += __shfl_xor_sync(0xffffffffu, s2, o);
                c2 += __shfl_xor_sync(0xffffffffu, c2, o);
            }
            bool done = (c2 == prev) || (c2 == 0);
            prev = c2;
            if (c2 > 0) tau = (s2 - 1.0f) / (float)c2;
            if (done) break;   // warp-uniform after shuffle reduction
        }
    }

    // attn = max(z - tau, 0): fp32 -> global; bf16 hi/lo -> planes (for GEMM2)
    {
        float* attn_row = attng + ((size_t)b * LDIM + grow) * LDIM;
        #pragma unroll
        for (int jj = 0; jj < 8; jj++) {
            int col = sub * 4 + 128 * jj;
            float a0 = fmaxf(z[jj*4+0] - tau, 0.0f);
            float a1 = fmaxf(z[jj*4+1] - tau, 0.0f);
            float a2 = fmaxf(z[jj*4+2] - tau, 0.0f);
            float a3 = fmaxf(z[jj*4+3] - tau, 0.0f);
            *(float4*)(attn_row + col) = make_float4(a0, a1, a2, a3);
            uint16_t h0,l0,h1,l1,h2,l2,h3,l3;
            bsplit(a0,h0,l0); bsplit(a1,h1,l1); bsplit(a2,h2,l2); bsplit(a3,h3,l3);
            *(uint2*)(a_hi + row * APROW + col) =
                make_uint2((uint32_t)h0 | ((uint32_t)h1<<16), (uint32_t)h2 | ((uint32_t)h3<<16));
            *(uint2*)(a_lo + row * APROW + col) =
                make_uint2((uint32_t)l0 | ((uint32_t)l1<<16), (uint32_t)l2 | ((uint32_t)l3<<16));
        }
    }

    // ==================== GEMM2: out = attn . v  (bf16x3 mma) ====================
    // warp w: k-step ksw = w&7 (16 k-rows per tile), n-half nh = w>>3 (32 of 64 d-cols)
    const int ksw = w & 7;
    const int nh  = w >> 3;
    const uint32_t ahi_b = sptr(a_hi), alo_b = sptr(a_lo);
    float d0[4], d1[4], d2[4], d3[4];
    #pragma unroll
    for (int nt = 0; nt < 4; nt++) { d0[nt]=d1[nt]=d2[nt]=d3[nt]=0.f; }

    for (int t = 0; t < LDIM / KT; t++) {
        __syncthreads();   // t=0: attn plane writes done; t>0: plane reuse
        // stage v tile [128 x 64] -> bf16 hi/lo planes
        {
            const int r  = tid >> 2;
            const int cs = (tid & 3) * 16;
            const float* src = vg + (size_t)(t * KT + r) * DDIM + cs;
            uint32_t hp[8], lp[8];
            #pragma unroll
            for (int i = 0; i < 4; i++) {
                float4 f = *(const float4*)(src + i * 4);
                uint16_t h0,l0,h1,l1,h2,l2,h3,l3;
                bsplit(f.x, h0, l0); bsplit(f.y, h1, l1);
                bsplit(f.z, h2, l2); bsplit(f.w, h3, l3);
                hp[i*2]   = (uint32_t)h0 | ((uint32_t)h1 << 16);
                hp[i*2+1] = (uint32_t)h2 | ((uint32_t)h3 << 16);
                lp[i*2]   = (uint32_t)l0 | ((uint32_t)l1 << 16);
                lp[i*2+1] = (uint32_t)l2 | ((uint32_t)l3 << 16);
            }
            uint32_t* dh = (uint32_t*)(k_hi + r * KPROW + cs);
            uint32_t* dl = (uint32_t*)(k_lo + r * KPROW + cs);
            *(uint4*)(dh)     = make_uint4(hp[0],hp[1],hp[2],hp[3]);
            *(uint4*)(dh + 4) = make_uint4(hp[4],hp[5],hp[6],hp[7]);
            *(uint4*)(dl)     = make_uint4(lp[0],lp[1],lp[2],lp[3]);
            *(uint4*)(dl + 4) = make_uint4(lp[4],lp[5],lp[6],lp[7]);
        }
        __syncthreads();

        const int ka = t * KT + 16 * ksw;   // global attn k-offset for this warp
        uint32_t ah0,ah1,ah2,ah3, al0,al1,al2,al3;
        LDSM_X4(ah0,ah1,ah2,ah3, ahi_b + (uint32_t)(arow * APROW + ka + acolofs) * 2);
        LDSM_X4(al0,al1,al2,al3, alo_b + (uint32_t)(arow * APROW + ka + acolofs) * 2);

        #pragma unroll
        for (int nt = 0; nt < 4; nt++) {
            const int nb2 = nh * 32 + nt * 8;
            const uint32_t bofs =
                (uint32_t)((16 * ksw + brow8 + bmat * 8) * KPROW + nb2) * 2;
            uint32_t bh0,bh1, bl0,bl1;
            LDSM_X2T(bh0,bh1, khi_b + bofs);
            LDSM_X2T(bl0,bl1, klo_b + bofs);
            MMA_BF16(d0[nt],d1[nt],d2[nt],d3[nt], ah0,ah1,ah2,ah3, bl0,bl1);
            MMA_BF16(d0[nt],d1[nt],d2[nt],d3[nt], al0,al1,al2,al3, bh0,bh1);
            MMA_BF16(d0[nt],d1[nt],d2[nt],d3[nt], ah0,ah1,ah2,ah3, bh0,bh1);
        }
    }
    __syncthreads();   // all v/attn plane reads done

    // cross-warp reduction: 8 partials per n-half, through red (aliases k/v planes)
    float* red = (float*)(smem + OFF_KHI);   // 16 * 16 * 32 fp32 = 32KB
    #pragma unroll
    for (int nt = 0; nt < 4; nt++) {
        const int nl = nt * 8 + 2 * tg;
        *(float2*)(red + w * 512 + gr * 32 + nl)       = make_float2(d0[nt], d1[nt]);
        *(float2*)(red + w * 512 + (gr + 8) * 32 + nl) = make_float2(d2[nt], d3[nt]);
    }
    __syncthreads();
    if (tid < 256) {
        const int o  = tid * 4;          // 0..1020
        const int m  = o >> 6;
        const int n  = o & 63;
        const int g  = (n >> 5) * 8;     // partial group base (warp ids)
        const int nl = n & 31;
        float4 sum = make_float4(0.f, 0.f, 0.f, 0.f);
        #pragma unroll
        for (int j = 0; j < 8; j++) {
            float4 p = *(float4*)(red + (g + j) * 512 + m * 32 + nl);
            sum.x += p.x; sum.y += p.y; sum.z += p.z; sum.w += p.w;
        }
        *(float4*)(outg + ((size_t)b * LDIM + q_row0 + m) * DDIM + n) = sum;
    }
}

extern "C" void kernel_launch(void* const* d_in, const int* in_sizes, int n_in,
                              void* d_out, int out_size)
{
    const float* q    = (const float*)d_in[0];
    const float* k    = (const float*)d_in[1];
    const float* v    = (const float*)d_in[2];
    const int*   mask = (const int*)d_in[3];

    float* out  = (float*)d_out;                                // [B, Lq, D]
    float* attn = (float*)d_out + (size_t)BDIM * LDIM * DDIM;   // [B, Lq, Lk]

    cudaFuncSetAttribute(sparse_attn_kernel,
                         cudaFuncAttributeMaxDynamicSharedMemorySize,
                         SMEM_BYTES);

    dim3 grid(LDIM / TQ, BDIM);   // (64, 64)
    dim3 block(NTHR);
    sparse_attn_kernel<<<grid, block, SMEM_BYTES>>>(q, k, v, mask, out, attn);
}

// round 11
// speedup vs baseline: 9.2671x; 1.0735x over previous
#include <cuda_runtime.h>
#include <cuda_bf16.h>
#include <math.h>
#include <stdint.h>

// Problem constants: B=64, Lq=Lk=1024, D=64
#define BDIM   64
#define LDIM   1024
#define DDIM   64
#define TQ     32          // q rows per CTA
#define KT     128         // k/v rows per smem tile
#define NTHR   512
#define SCROW  1036        // fp32 score smem stride (floats)
#define APROW  1032        // attn bf16 plane stride (bf16 elems)
#define KPROW  72          // k/v bf16 plane stride (bf16) -> 144B rows
#define QPROW  72

// smem byte layout:
//  [0)      q_hi 32x72 bf16 (4608) | q_lo (4608)                    -> 9216
//  [9216)   k_hi 128x72 bf16 (18432) | k_lo (18432)                 -> 46080
//  [46080)  sc fp32 32x1036 (132608)
//           aliases: attn bf16 hi/lo planes (2 x 32x1032x2 = 132096)
//                    GEMM2 reduction scratch (64KB)
#define OFF_QHI 0
#define OFF_QLO 4608
#define OFF_KHI 9216
#define OFF_KLO 27648
#define OFF_SC  46080
#define SMEM_BYTES 178688

__device__ __forceinline__ uint32_t sptr(const void* p) {
    return (uint32_t)__cvta_generic_to_shared(p);
}
__device__ __forceinline__ void bsplit(float x, uint16_t& h, uint16_t& l) {
    __nv_bfloat16 bh = __float2bfloat16(x);
    float r = x - __bfloat162float(bh);
    __nv_bfloat16 bl = __float2bfloat16(r);
    h = __bfloat16_as_ushort(bh);
    l = __bfloat16_as_ushort(bl);
}

#define LDSM_X4(r0,r1,r2,r3, a)                                                  \
    asm volatile("ldmatrix.sync.aligned.m8n8.x4.shared.b16 {%0,%1,%2,%3}, [%4];" \
        : "=r"(r0), "=r"(r1), "=r"(r2), "=r"(r3) : "r"(a))
#define LDSM_X2(r0,r1, a)                                                        \
    asm volatile("ldmatrix.sync.aligned.m8n8.x2.shared.b16 {%0,%1}, [%2];"       \
        : "=r"(r0), "=r"(r1) : "r"(a))
#define LDSM_X2T(r0,r1, a)                                                       \
    asm volatile("ldmatrix.sync.aligned.m8n8.x2.trans.shared.b16 {%0,%1}, [%2];" \
        : "=r"(r0), "=r"(r1) : "r"(a))
#define MMA_BF16(c0,c1,c2,c3, a0,a1,a2,a3, b0,b1)                                \
    asm volatile("mma.sync.aligned.m16n8k16.row.col.f32.bf16.bf16.f32 "          \
        "{%0,%1,%2,%3}, {%4,%5,%6,%7}, {%8,%9}, {%0,%1,%2,%3};"                  \
        : "+f"(c0), "+f"(c1), "+f"(c2), "+f"(c3)                                 \
        : "r"(a0), "r"(a1), "r"(a2), "r"(a3), "r"(b0), "r"(b1))

// stage one [128 x 64] fp32 tile -> bf16 hi/lo planes (all 512 threads)
__device__ __forceinline__ void stage_tile_bf16(const float* __restrict__ src_base,
                                                uint16_t* hi, uint16_t* lo, int tid)
{
    const int r  = tid >> 2;
    const int cs = (tid & 3) * 16;
    const float* src = src_base + (size_t)r * DDIM + cs;
    uint32_t hp[8], lp[8];
    #pragma unroll
    for (int i = 0; i < 4; i++) {
        float4 f = *(const float4*)(src + i * 4);
        uint16_t h0,l0,h1,l1,h2,l2,h3,l3;
        bsplit(f.x, h0, l0); bsplit(f.y, h1, l1);
        bsplit(f.z, h2, l2); bsplit(f.w, h3, l3);
        hp[i*2]   = (uint32_t)h0 | ((uint32_t)h1 << 16);
        hp[i*2+1] = (uint32_t)h2 | ((uint32_t)h3 << 16);
        lp[i*2]   = (uint32_t)l0 | ((uint32_t)l1 << 16);
        lp[i*2+1] = (uint32_t)l2 | ((uint32_t)l3 << 16);
    }
    uint32_t* dh = (uint32_t*)(hi + r * KPROW + cs);
    uint32_t* dl = (uint32_t*)(lo + r * KPROW + cs);
    *(uint4*)(dh)     = make_uint4(hp[0],hp[1],hp[2],hp[3]);
    *(uint4*)(dh + 4) = make_uint4(hp[4],hp[5],hp[6],hp[7]);
    *(uint4*)(dl)     = make_uint4(lp[0],lp[1],lp[2],lp[3]);
    *(uint4*)(dl + 4) = make_uint4(lp[4],lp[5],lp[6],lp[7]);
}

__global__ __launch_bounds__(NTHR, 1)
void sparse_attn_kernel(const float* __restrict__ qg_,
                        const float* __restrict__ kg_,
                        const float* __restrict__ vg_,
                        const int* __restrict__ maskg,
                        float* __restrict__ outg,
                        float* __restrict__ attng)
{
    extern __shared__ char smem[];
    uint16_t* q_hi = (uint16_t*)(smem + OFF_QHI);
    uint16_t* q_lo = (uint16_t*)(smem + OFF_QLO);
    uint16_t* k_hi = (uint16_t*)(smem + OFF_KHI);   // also v planes
    uint16_t* k_lo = (uint16_t*)(smem + OFF_KLO);
    float*    sc_s = (float*)   (smem + OFF_SC);
    uint16_t* a_hi = (uint16_t*)(smem + OFF_SC);    // attn hi plane (aliases sc)
    uint16_t* a_lo = a_hi + TQ * APROW;             // attn lo plane

    const int qt   = blockIdx.x;            // 0..31
    const int b    = blockIdx.y;            // 0..63
    const int tid  = threadIdx.x;
    const int w    = tid >> 5;              // warp 0..15
    const int lane = tid & 31;
    const int gr   = lane >> 2;             // 0..7
    const int tg   = lane & 3;              // 0..3

    const int q_row0 = qt * TQ;
    const float* qg = qg_ + ((size_t)b * LDIM + q_row0) * DDIM;
    const float* kg = kg_ + (size_t)b * LDIM * DDIM;
    const float* vg = vg_ + (size_t)b * LDIM * DDIM;

    // ldmatrix lane addressing
    const int g4      = lane >> 3;
    const int arow    = (lane & 7) | ((g4 & 1) << 3);   // A row within 16
    const int acolofs = (g4 >> 1) << 3;                 // A +0/+8 k-offset
    const int li      = lane & 15;
    const int brow8   = li & 7;
    const int bmat    = li >> 3;

    // ---- stage q tile (32x64), scale 1/8, split -> bf16 hi/lo planes ----
    if (tid < 128) {
        const int r  = tid >> 2;
        const int cs = (tid & 3) * 16;
        const float* src = qg + r * DDIM + cs;
        uint32_t hp[8], lp[8];
        #pragma unroll
        for (int i = 0; i < 4; i++) {
            float4 f = *(const float4*)(src + i * 4);
            uint16_t h0,l0,h1,l1,h2,l2,h3,l3;
            bsplit(f.x * 0.125f, h0, l0); bsplit(f.y * 0.125f, h1, l1);
            bsplit(f.z * 0.125f, h2, l2); bsplit(f.w * 0.125f, h3, l3);
            hp[i*2]   = (uint32_t)h0 | ((uint32_t)h1 << 16);
            hp[i*2+1] = (uint32_t)h2 | ((uint32_t)h3 << 16);
            lp[i*2]   = (uint32_t)l0 | ((uint32_t)l1 << 16);
            lp[i*2+1] = (uint32_t)l2 | ((uint32_t)l3 << 16);
        }
        uint32_t* dh = (uint32_t*)(q_hi + r * QPROW + cs);
        uint32_t* dl = (uint32_t*)(q_lo + r * QPROW + cs);
        *(uint4*)(dh)     = make_uint4(hp[0],hp[1],hp[2],hp[3]);
        *(uint4*)(dh + 4) = make_uint4(hp[4],hp[5],hp[6],hp[7]);
        *(uint4*)(dl)     = make_uint4(lp[0],lp[1],lp[2],lp[3]);
        *(uint4*)(dl + 4) = make_uint4(lp[4],lp[5],lp[6],lp[7]);
    }
    __syncthreads();

    const uint32_t qhi_b = sptr(q_hi), qlo_b = sptr(q_lo);
    const uint32_t khi_b = sptr(k_hi), klo_b = sptr(k_lo);

    // ---- hoist q fragments into registers: [rowgroup][kc] hi/lo ----
    uint32_t qa_h[2][4][4], qa_l[2][4][4];
    #pragma unroll
    for (int rg = 0; rg < 2; rg++)
        #pragma unroll
        for (int kc = 0; kc < 4; kc++) {
            const uint32_t ao =
                (uint32_t)((rg * 16 + arow) * QPROW + kc * 16 + acolofs) * 2;
            LDSM_X4(qa_h[rg][kc][0], qa_h[rg][kc][1], qa_h[rg][kc][2], qa_h[rg][kc][3],
                    qhi_b + ao);
            LDSM_X4(qa_l[rg][kc][0], qa_l[rg][kc][1], qa_l[rg][kc][2], qa_l[rg][kc][3],
                    qlo_b + ao);
        }

    // ==================== GEMM1: scores = (q/8) . k^T  (bf16x3 mma) ====================
    const int nb = 8 * w;   // warp's 8 score-cols within each tile
    for (int t = 0; t < LDIM / KT; t++) {
        __syncthreads();
        stage_tile_bf16(kg + (size_t)t * KT * DDIM, k_hi, k_lo, tid);
        __syncthreads();

        float c0[2] = {0.f,0.f}, c1[2] = {0.f,0.f}, c2[2] = {0.f,0.f}, c3[2] = {0.f,0.f};
        #pragma unroll
        for (int kc = 0; kc < 4; kc++) {
            uint32_t bh0,bh1, bl0,bl1;
            const uint32_t bofs = (uint32_t)((nb + brow8) * KPROW + kc * 16 + bmat * 8) * 2;
            LDSM_X2(bh0,bh1, khi_b + bofs);
            LDSM_X2(bl0,bl1, klo_b + bofs);
            #pragma unroll
            for (int rg = 0; rg < 2; rg++) {
                MMA_BF16(c0[rg],c1[rg],c2[rg],c3[rg],
                         qa_h[rg][kc][0],qa_h[rg][kc][1],qa_h[rg][kc][2],qa_h[rg][kc][3],
                         bl0,bl1);
                MMA_BF16(c0[rg],c1[rg],c2[rg],c3[rg],
                         qa_l[rg][kc][0],qa_l[rg][kc][1],qa_l[rg][kc][2],qa_l[rg][kc][3],
                         bh0,bh1);
                MMA_BF16(c0[rg],c1[rg],c2[rg],c3[rg],
                         qa_h[rg][kc][0],qa_h[rg][kc][1],qa_h[rg][kc][2],qa_h[rg][kc][3],
                         bh0,bh1);
            }
        }
        #pragma unroll
        for (int rg = 0; rg < 2; rg++) {
            float* sp = sc_s + (rg * 16 + gr) * SCROW + t * KT + nb + 2 * tg;
            *(float2*)sp               = make_float2(c0[rg], c1[rg]);
            *(float2*)(sp + 8 * SCROW) = make_float2(c2[rg], c3[rg]);
        }
    }
    __syncthreads();

    // ============ mask + sparsemax (Michelot; warp handles 2 rows sequentially) ============
    float taus[2];
    float az[2][32];   // masked scores for both rows (kept for attn emit)
    #pragma unroll
    for (int rr = 0; rr < 2; rr++) {
        const int row  = w * 2 + rr;
        const int grow = q_row0 + row;
        float* z = az[rr];
        {
            const int4* m4 = (const int4*)(maskg + ((size_t)b * LDIM + grow) * LDIM);
            #pragma unroll
            for (int jj = 0; jj < 8; jj++) {
                int col = lane * 4 + 128 * jj;
                int4   mb = m4[col >> 2];
                float4 s  = *(float4*)(sc_s + row * SCROW + col);
                z[jj*4+0] = mb.x ? -INFINITY : s.x;
                z[jj*4+1] = mb.y ? -INFINITY : s.y;
                z[jj*4+2] = mb.z ? -INFINITY : s.z;
                z[jj*4+3] = mb.w ? -INFINITY : s.w;
            }
        }
        float s = 0.0f; int c = 0;
        #pragma unroll
        for (int i = 0; i < 32; i++)
            if (z[i] > -INFINITY) { s += z[i]; c++; }
        #pragma unroll
        for (int o = 16; o >= 1; o >>= 1) {
            s += __shfl_xor_sync(0xffffffffu, s, o);
            c += __shfl_xor_sync(0xffffffffu, c, o);
        }
        float tau = (c > 0) ? (s - 1.0f) / (float)c : INFINITY;
        int prev = c;
        for (int it = 0; it < 64; it++) {
            float s2 = 0.0f; int c2 = 0;
            #pragma unroll
            for (int i = 0; i < 32; i++)
                if (z[i] > tau) { s2 += z[i]; c2++; }
            #pragma unroll
            for (int o = 16; o >= 1; o >>= 1) {
                s2 += __shfl_xor_sync(0xffffffffu, s2, o);
                c2 += __shfl_xor_sync(0xffffffffu, c2, o);
            }
            bool done = (c2 == prev) || (c2 == 0);
            prev = c2;
            if (c2 > 0) tau = (s2 - 1.0f) / (float)c2;
            if (done) break;   // warp-uniform
        }
        taus[rr] = tau;
    }
    __syncthreads();   // all score reads complete before attn planes overwrite region

    // attn = max(z - tau, 0): fp32 -> global; bf16 hi/lo -> planes
    #pragma unroll
    for (int rr = 0; rr < 2; rr++) {
        const int row  = w * 2 + rr;
        const int grow = q_row0 + row;
        const float tau = taus[rr];
        float* z = az[rr];
        float* attn_row = attng + ((size_t)b * LDIM + grow) * LDIM;
        #pragma unroll
        for (int jj = 0; jj < 8; jj++) {
            int col = lane * 4 + 128 * jj;
            float a0 = fmaxf(z[jj*4+0] - tau, 0.0f);
            float a1 = fmaxf(z[jj*4+1] - tau, 0.0f);
            float a2 = fmaxf(z[jj*4+2] - tau, 0.0f);
            float a3 = fmaxf(z[jj*4+3] - tau, 0.0f);
            *(float4*)(attn_row + col) = make_float4(a0, a1, a2, a3);
            uint16_t h0,l0,h1,l1,h2,l2,h3,l3;
            bsplit(a0,h0,l0); bsplit(a1,h1,l1); bsplit(a2,h2,l2); bsplit(a3,h3,l3);
            *(uint2*)(a_hi + row * APROW + col) =
                make_uint2((uint32_t)h0 | ((uint32_t)h1<<16), (uint32_t)h2 | ((uint32_t)h3<<16));
            *(uint2*)(a_lo + row * APROW + col) =
                make_uint2((uint32_t)l0 | ((uint32_t)l1<<16), (uint32_t)l2 | ((uint32_t)l3<<16));
        }
    }

    // ==================== GEMM2: out = attn . v  (bf16x3 mma) ====================
    // warp w: k-step ksw = w&7, n-half nh = w>>3; 2 rowgroups of attn rows
    const int ksw = w & 7;
    const int nh  = w >> 3;
    const uint32_t ahi_b = sptr(a_hi), alo_b = sptr(a_lo);
    float d0[2][4], d1[2][4], d2[2][4], d3[2][4];
    #pragma unroll
    for (int rg = 0; rg < 2; rg++)
        #pragma unroll
        for (int nt = 0; nt < 4; nt++) { d0[rg][nt]=d1[rg][nt]=d2[rg][nt]=d3[rg][nt]=0.f; }

    for (int t = 0; t < LDIM / KT; t++) {
        __syncthreads();   // t=0: attn planes written; t>0: v plane reuse
        stage_tile_bf16(vg + (size_t)t * KT * DDIM, k_hi, k_lo, tid);
        __syncthreads();

        const int ka = t * KT + 16 * ksw;
        uint32_t ah[2][4], al[2][4];
        #pragma unroll
        for (int rg = 0; rg < 2; rg++) {
            const uint32_t ao =
                (uint32_t)((rg * 16 + arow) * APROW + ka + acolofs) * 2;
            LDSM_X4(ah[rg][0],ah[rg][1],ah[rg][2],ah[rg][3], ahi_b + ao);
            LDSM_X4(al[rg][0],al[rg][1],al[rg][2],al[rg][3], alo_b + ao);
        }
        #pragma unroll
        for (int nt = 0; nt < 4; nt++) {
            const int nb2 = nh * 32 + nt * 8;
            const uint32_t bofs =
                (uint32_t)((16 * ksw + brow8 + bmat * 8) * KPROW + nb2) * 2;
            uint32_t bh0,bh1, bl0,bl1;
            LDSM_X2T(bh0,bh1, khi_b + bofs);
            LDSM_X2T(bl0,bl1, klo_b + bofs);
            #pragma unroll
            for (int rg = 0; rg < 2; rg++) {
                MMA_BF16(d0[rg][nt],d1[rg][nt],d2[rg][nt],d3[rg][nt],
                         ah[rg][0],ah[rg][1],ah[rg][2],ah[rg][3], bl0,bl1);
                MMA_BF16(d0[rg][nt],d1[rg][nt],d2[rg][nt],d3[rg][nt],
                         al[rg][0],al[rg][1],al[rg][2],al[rg][3], bh0,bh1);
                MMA_BF16(d0[rg][nt],d1[rg][nt],d2[rg][nt],d3[rg][nt],
                         ah[rg][0],ah[rg][1],ah[rg][2],ah[rg][3], bh0,bh1);
            }
        }
    }
    __syncthreads();   // attn/v plane reads done -> reduction may overwrite region

    // cross-warp reduction: 8 k-slice partials per n-half, via sc region
    float* red = (float*)(smem + OFF_SC);   // 16 warps * 32 rows * 32 cols = 64KB
    #pragma unroll
    for (int rg = 0; rg < 2; rg++)
        #pragma unroll
        for (int nt = 0; nt < 4; nt++) {
            const int nl = nt * 8 + 2 * tg;
            float* rp = red + w * 1024 + (rg * 16 + gr) * 32 + nl;
            *(float2*)rp            = make_float2(d0[rg][nt], d1[rg][nt]);
            *(float2*)(rp + 8 * 32) = make_float2(d2[rg][nt], d3[rg][nt]);
        }
    __syncthreads();
    {
        const int o  = tid * 4;          // 0..2044
        const int m  = o >> 6;           // 0..31
        const int n  = o & 63;
        const int wb = (n >> 5) * 8;     // warps holding this n-half
        const int nl = n & 31;
        float4 sum = make_float4(0.f, 0.f, 0.f, 0.f);
        #pragma unroll
        for (int j = 0; j < 8; j++) {
            float4 p = *(float4*)(red + (wb + j) * 1024 + m * 32 + nl);
            sum.x += p.x; sum.y += p.y; sum.z += p.z; sum.w += p.w;
        }
        *(float4*)(outg + ((size_t)b * LDIM + q_row0 + m) * DDIM + n) = sum;
    }
}

extern "C" void kernel_launch(void* const* d_in, const int* in_sizes, int n_in,
                              void* d_out, int out_size)
{
    const float* q    = (const float*)d_in[0];
    const float* k    = (const float*)d_in[1];
    const float* v    = (const float*)d_in[2];
    const int*   mask = (const int*)d_in[3];

    float* out  = (float*)d_out;                                // [B, Lq, D]
    float* attn = (float*)d_out + (size_t)BDIM * LDIM * DDIM;   // [B, Lq, Lk]

    cudaFuncSetAttribute(sparse_attn_kernel,
                         cudaFuncAttributeMaxDynamicSharedMemorySize,
                         SMEM_BYTES);

    dim3 grid(LDIM / TQ, BDIM);   // (32, 64)
    dim3 block(NTHR);
    sparse_attn_kernel<<<grid, block, SMEM_BYTES>>>(q, k, v, mask, out, attn);
}

// round 13
// speedup vs baseline: 11.2825x; 1.2175x over previous
#include <cuda_runtime.h>
#include <cuda_bf16.h>
#include <math.h>
#include <stdint.h>

// Problem constants: B=64, Lq=Lk=1024, D=64
#define BDIM   64
#define LDIM   1024
#define DDIM   64
#define TQ     32          // q rows per CTA
#define KT     128         // k/v rows per smem tile
#define NTHR   512
#define SCROW  1036        // fp32 score smem stride (floats)
#define APROW  1032        // attn bf16 plane stride (bf16 elems)
#define KPROW  72          // k/v bf16 plane stride (bf16) -> 144B rows
#define QPROW  72

// smem byte layout:
//  [0)      q_hi 32x72 bf16 (4608) | q_lo (4608)                      -> 9216
//  [9216)   kv buf0: hi 128x72 (18432) | lo (18432)                   -> 46080
//  [46080)  kv buf1: hi | lo                                          -> 82944
//  [82944)  sc fp32 32x1036 (132608)
//           aliases: attn bf16 hi/lo planes (2 x 32x1032x2 = 132096)
//                    GEMM2 reduction scratch (64KB)
#define OFF_QHI 0
#define OFF_QLO 4608
#define OFF_K0  9216
#define KBUF_SZ 36864
#define OFF_SC  82944
#define SMEM_BYTES 215552

__device__ __forceinline__ uint32_t sptr(const void* p) {
    return (uint32_t)__cvta_generic_to_shared(p);
}
__device__ __forceinline__ void bsplit(float x, uint16_t& h, uint16_t& l) {
    __nv_bfloat16 bh = __float2bfloat16(x);
    float r = x - __bfloat162float(bh);
    __nv_bfloat16 bl = __float2bfloat16(r);
    h = __bfloat16_as_ushort(bh);
    l = __bfloat16_as_ushort(bl);
}

#define LDSM_X4(r0,r1,r2,r3, a)                                                  \
    asm volatile("ldmatrix.sync.aligned.m8n8.x4.shared.b16 {%0,%1,%2,%3}, [%4];" \
        : "=r"(r0), "=r"(r1), "=r"(r2), "=r"(r3) : "r"(a))
#define LDSM_X2(r0,r1, a)                                                        \
    asm volatile("ldmatrix.sync.aligned.m8n8.x2.shared.b16 {%0,%1}, [%2];"       \
        : "=r"(r0), "=r"(r1) : "r"(a))
#define LDSM_X2T(r0,r1, a)                                                       \
    asm volatile("ldmatrix.sync.aligned.m8n8.x2.trans.shared.b16 {%0,%1}, [%2];" \
        : "=r"(r0), "=r"(r1) : "r"(a))
#define MMA_BF16(c0,c1,c2,c3, a0,a1,a2,a3, b0,b1)                                \
    asm volatile("mma.sync.aligned.m16n8k16.row.col.f32.bf16.bf16.f32 "          \
        "{%0,%1,%2,%3}, {%4,%5,%6,%7}, {%8,%9}, {%0,%1,%2,%3};"                  \
        : "+f"(c0), "+f"(c1), "+f"(c2), "+f"(c3)                                 \
        : "r"(a0), "r"(a1), "r"(a2), "r"(a3), "r"(b0), "r"(b1))

// prefetch this thread's 16 floats of a [128 x 64] tile into registers
__device__ __forceinline__ void prefetch_tile(const float* __restrict__ src_base,
                                              int tid, float4 pf[4])
{
    const int r  = tid >> 2;
    const int cs = (tid & 3) * 16;
    const float* src = src_base + (size_t)r * DDIM + cs;
    #pragma unroll
    for (int i = 0; i < 4; i++) pf[i] = *(const float4*)(src + i * 4);
}

// convert prefetched registers -> bf16 hi/lo planes
__device__ __forceinline__ void convert_tile(const float4 pf[4],
                                             uint16_t* hi, uint16_t* lo, int tid)
{
    const int r  = tid >> 2;
    const int cs = (tid & 3) * 16;
    uint32_t hp[8], lp[8];
    #pragma unroll
    for (int i = 0; i < 4; i++) {
        uint16_t h0,l0,h1,l1,h2,l2,h3,l3;
        bsplit(pf[i].x, h0, l0); bsplit(pf[i].y, h1, l1);
        bsplit(pf[i].z, h2, l2); bsplit(pf[i].w, h3, l3);
        hp[i*2]   = (uint32_t)h0 | ((uint32_t)h1 << 16);
        hp[i*2+1] = (uint32_t)h2 | ((uint32_t)h3 << 16);
        lp[i*2]   = (uint32_t)l0 | ((uint32_t)l1 << 16);
        lp[i*2+1] = (uint32_t)l2 | ((uint32_t)l3 << 16);
    }
    uint32_t* dh = (uint32_t*)(hi + r * KPROW + cs);
    uint32_t* dl = (uint32_t*)(lo + r * KPROW + cs);
    *(uint4*)(dh)     = make_uint4(hp[0],hp[1],hp[2],hp[3]);
    *(uint4*)(dh + 4) = make_uint4(hp[4],hp[5],hp[6],hp[7]);
    *(uint4*)(dl)     = make_uint4(lp[0],lp[1],lp[2],lp[3]);
    *(uint4*)(dl + 4) = make_uint4(lp[4],lp[5],lp[6],lp[7]);
}

__global__ __launch_bounds__(NTHR, 1)
void sparse_attn_kernel(const float* __restrict__ qg_,
                        const float* __restrict__ kg_,
                        const float* __restrict__ vg_,
                        const int* __restrict__ maskg,
                        float* __restrict__ outg,
                        float* __restrict__ attng)
{
    extern __shared__ char smem[];
    uint16_t* q_hi = (uint16_t*)(smem + OFF_QHI);
    uint16_t* q_lo = (uint16_t*)(smem + OFF_QLO);
    float*    sc_s = (float*)   (smem + OFF_SC);
    uint16_t* a_hi = (uint16_t*)(smem + OFF_SC);    // attn hi plane (aliases sc)
    uint16_t* a_lo = a_hi + TQ * APROW;             // attn lo plane

    uint16_t* kbuf_hi[2] = { (uint16_t*)(smem + OFF_K0),
                             (uint16_t*)(smem + OFF_K0 + KBUF_SZ) };
    uint16_t* kbuf_lo[2] = { (uint16_t*)(smem + OFF_K0 + KBUF_SZ/2),
                             (uint16_t*)(smem + OFF_K0 + KBUF_SZ + KBUF_SZ/2) };

    const int qt   = blockIdx.x;            // 0..31
    const int b    = blockIdx.y;            // 0..63
    const int tid  = threadIdx.x;
    const int w    = tid >> 5;              // warp 0..15
    const int lane = tid & 31;
    const int gr   = lane >> 2;             // 0..7
    const int tg   = lane & 3;              // 0..3

    const int q_row0 = qt * TQ;
    const float* qg = qg_ + ((size_t)b * LDIM + q_row0) * DDIM;
    const float* kg = kg_ + (size_t)b * LDIM * DDIM;
    const float* vg = vg_ + (size_t)b * LDIM * DDIM;

    // ldmatrix lane addressing
    const int g4      = lane >> 3;
    const int arow    = (lane & 7) | ((g4 & 1) << 3);   // A row within 16
    const int acolofs = (g4 >> 1) << 3;                 // A +0/+8 k-offset
    const int li      = lane & 15;
    const int brow8   = li & 7;
    const int bmat    = li >> 3;

    float4 pf[4];
    prefetch_tile(kg, tid, pf);             // k tile 0 (issued earliest)

    // ---- stage q tile (32x64), scale 1/8, split -> bf16 hi/lo planes ----
    if (tid < 128) {
        const int r  = tid >> 2;
        const int cs = (tid & 3) * 16;
        const float* src = qg + r * DDIM + cs;
        uint32_t hp[8], lp[8];
        #pragma unroll
        for (int i = 0; i < 4; i++) {
            float4 f = *(const float4*)(src + i * 4);
            uint16_t h0,l0,h1,l1,h2,l2,h3,l3;
            bsplit(f.x * 0.125f, h0, l0); bsplit(f.y * 0.125f, h1, l1);
            bsplit(f.z * 0.125f, h2, l2); bsplit(f.w * 0.125f, h3, l3);
            hp[i*2]   = (uint32_t)h0 | ((uint32_t)h1 << 16);
            hp[i*2+1] = (uint32_t)h2 | ((uint32_t)h3 << 16);
            lp[i*2]   = (uint32_t)l0 | ((uint32_t)l1 << 16);
            lp[i*2+1] = (uint32_t)l2 | ((uint32_t)l3 << 16);
        }
        uint32_t* dh = (uint32_t*)(q_hi + r * QPROW + cs);
        uint32_t* dl = (uint32_t*)(q_lo + r * QPROW + cs);
        *(uint4*)(dh)     = make_uint4(hp[0],hp[1],hp[2],hp[3]);
        *(uint4*)(dh + 4) = make_uint4(hp[4],hp[5],hp[6],hp[7]);
        *(uint4*)(dl)     = make_uint4(lp[0],lp[1],lp[2],lp[3]);
        *(uint4*)(dl + 4) = make_uint4(lp[4],lp[5],lp[6],lp[7]);
    }
    convert_tile(pf, kbuf_hi[0], kbuf_lo[0], tid);   // k tile 0 -> buf0
    __syncthreads();   // q planes + k buf0 ready

    // ---- hoist q fragments into registers: [rowgroup][kc] hi/lo ----
    const uint32_t qhi_b = sptr(q_hi), qlo_b = sptr(q_lo);
    uint32_t qa_h[2][4][4], qa_l[2][4][4];
    #pragma unroll
    for (int rg = 0; rg < 2; rg++)
        #pragma unroll
        for (int kc = 0; kc < 4; kc++) {
            const uint32_t ao =
                (uint32_t)((rg * 16 + arow) * QPROW + kc * 16 + acolofs) * 2;
            LDSM_X4(qa_h[rg][kc][0], qa_h[rg][kc][1], qa_h[rg][kc][2], qa_h[rg][kc][3],
                    qhi_b + ao);
            LDSM_X4(qa_l[rg][kc][0], qa_l[rg][kc][1], qa_l[rg][kc][2], qa_l[rg][kc][3],
                    qlo_b + ao);
        }

    // ==================== GEMM1: scores = (q/8) . k^T  (bf16x3, pipelined) ====================
    const int nb = 8 * w;   // warp's 8 score-cols within each tile
    for (int t = 0; t < LDIM / KT; t++) {
        if (t < LDIM / KT - 1)
            prefetch_tile(kg + (size_t)(t + 1) * KT * DDIM, tid, pf);

        const uint32_t khi_b = sptr(kbuf_hi[t & 1]);
        const uint32_t klo_b = sptr(kbuf_lo[t & 1]);
        float c0[2] = {0.f,0.f}, c1[2] = {0.f,0.f}, c2[2] = {0.f,0.f}, c3[2] = {0.f,0.f};
        #pragma unroll
        for (int kc = 0; kc < 4; kc++) {
            uint32_t bh0,bh1, bl0,bl1;
            const uint32_t bofs = (uint32_t)((nb + brow8) * KPROW + kc * 16 + bmat * 8) * 2;
            LDSM_X2(bh0,bh1, khi_b + bofs);
            LDSM_X2(bl0,bl1, klo_b + bofs);
            #pragma unroll
            for (int rg = 0; rg < 2; rg++) {
                MMA_BF16(c0[rg],c1[rg],c2[rg],c3[rg],
                         qa_h[rg][kc][0],qa_h[rg][kc][1],qa_h[rg][kc][2],qa_h[rg][kc][3],
                         bl0,bl1);
                MMA_BF16(c0[rg],c1[rg],c2[rg],c3[rg],
                         qa_l[rg][kc][0],qa_l[rg][kc][1],qa_l[rg][kc][2],qa_l[rg][kc][3],
                         bh0,bh1);
                MMA_BF16(c0[rg],c1[rg],c2[rg],c3[rg],
                         qa_h[rg][kc][0],qa_h[rg][kc][1],qa_h[rg][kc][2],qa_h[rg][kc][3],
                         bh0,bh1);
            }
        }
        #pragma unroll
        for (int rg = 0; rg < 2; rg++) {
            float* sp = sc_s + (rg * 16 + gr) * SCROW + t * KT + nb + 2 * tg;
            *(float2*)sp               = make_float2(c0[rg], c1[rg]);
            *(float2*)(sp + 8 * SCROW) = make_float2(c2[rg], c3[rg]);
        }
        if (t < LDIM / KT - 1)
            convert_tile(pf, kbuf_hi[(t + 1) & 1], kbuf_lo[(t + 1) & 1], tid);
        __syncthreads();   // next buffer ready; this buffer's reads complete
    }

    // ============ mask + sparsemax (Michelot; warp handles 2 rows sequentially) ============
    float taus[2];
    float az[2][32];
    #pragma unroll
    for (int rr = 0; rr < 2; rr++) {
        const int row  = w * 2 + rr;
        const int grow = q_row0 + row;
        float* z = az[rr];
        {
            const int4* m4 = (const int4*)(maskg + ((size_t)b * LDIM + grow) * LDIM);
            #pragma unroll
            for (int jj = 0; jj < 8; jj++) {
                int col = lane * 4 + 128 * jj;
                int4   mb = m4[col >> 2];
                float4 s  = *(float4*)(sc_s + row * SCROW + col);
                z[jj*4+0] = mb.x ? -INFINITY : s.x;
                z[jj*4+1] = mb.y ? -INFINITY : s.y;
                z[jj*4+2] = mb.z ? -INFINITY : s.z;
                z[jj*4+3] = mb.w ? -INFINITY : s.w;
            }
        }
        float s = 0.0f; int c = 0;
        #pragma unroll
        for (int i = 0; i < 32; i++)
            if (z[i] > -INFINITY) { s += z[i]; c++; }
        #pragma unroll
        for (int o = 16; o >= 1; o >>= 1) {
            s += __shfl_xor_sync(0xffffffffu, s, o);
            c += __shfl_xor_sync(0xffffffffu, c, o);
        }
        float tau = (c > 0) ? (s - 1.0f) / (float)c : INFINITY;
        int prev = c;
        for (int it = 0; it < 64; it++) {
            float s2 = 0.0f; int c2 = 0;
            #pragma unroll
            for (int i = 0; i < 32; i++)
                if (z[i] > tau) { s2 += z[i]; c2++; }
            #pragma unroll
            for (int o = 16; o >= 1; o >>= 1) {
                s2 += __shfl_xor_sync(0xffffffffu, s2, o);
                c2 += __shfl_xor_sync(0xffffffffu, c2, o);
            }
            bool done = (c2 == prev) || (c2 == 0);
            prev = c2;
            if (c2 > 0) tau = (s2 - 1.0f) / (float)c2;
            if (done) break;   // warp-uniform
        }
        taus[rr] = tau;
    }
    __syncthreads();   // all score reads done before attn planes overwrite region

    // attn = max(z - tau, 0): fp32 -> global; bf16 hi/lo -> planes
    #pragma unroll
    for (int rr = 0; rr < 2; rr++) {
        const int row  = w * 2 + rr;
        const int grow = q_row0 + row;
        const float tau = taus[rr];
        float* z = az[rr];
        float* attn_row = attng + ((size_t)b * LDIM + grow) * LDIM;
        #pragma unroll
        for (int jj = 0; jj < 8; jj++) {
            int col = lane * 4 + 128 * jj;
            float a0 = fmaxf(z[jj*4+0] - tau, 0.0f);
            float a1 = fmaxf(z[jj*4+1] - tau, 0.0f);
            float a2 = fmaxf(z[jj*4+2] - tau, 0.0f);
            float a3 = fmaxf(z[jj*4+3] - tau, 0.0f);
            *(float4*)(attn_row + col) = make_float4(a0, a1, a2, a3);
            uint16_t h0,l0,h1,l1,h2,l2,h3,l3;
            bsplit(a0,h0,l0); bsplit(a1,h1,l1); bsplit(a2,h2,l2); bsplit(a3,h3,l3);
            *(uint2*)(a_hi + row * APROW + col) =
                make_uint2((uint32_t)h0 | ((uint32_t)h1<<16), (uint32_t)h2 | ((uint32_t)h3<<16));
            *(uint2*)(a_lo + row * APROW + col) =
                make_uint2((uint32_t)l0 | ((uint32_t)l1<<16), (uint32_t)l2 | ((uint32_t)l3<<16));
        }
    }

    // ==================== GEMM2: out = attn . v  (bf16x3, pipelined) ====================
    const int ksw = w & 7;
    const int nh  = w >> 3;
    const uint32_t ahi_b = sptr(a_hi), alo_b = sptr(a_lo);
    float d0[2][4], d1[2][4], d2[2][4], d3[2][4];
    #pragma unroll
    for (int rg = 0; rg < 2; rg++)
        #pragma unroll
        for (int nt = 0; nt < 4; nt++) { d0[rg][nt]=d1[rg][nt]=d2[rg][nt]=d3[rg][nt]=0.f; }

    prefetch_tile(vg, tid, pf);                        // v tile 0
    convert_tile(pf, kbuf_hi[0], kbuf_lo[0], tid);     // safe: k reads long done
    __syncthreads();   // attn planes + v buf0 ready

    for (int t = 0; t < LDIM / KT; t++) {
        if (t < LDIM / KT - 1)
            prefetch_tile(vg + (size_t)(t + 1) * KT * DDIM, tid, pf);

        const uint32_t vhi_b = sptr(kbuf_hi[t & 1]);
        const uint32_t vlo_b = sptr(kbuf_lo[t & 1]);
        const int ka = t * KT + 16 * ksw;
        uint32_t ah[2][4], al[2][4];
        #pragma unroll
        for (int rg = 0; rg < 2; rg++) {
            const uint32_t ao =
                (uint32_t)((rg * 16 + arow) * APROW + ka + acolofs) * 2;
            LDSM_X4(ah[rg][0],ah[rg][1],ah[rg][2],ah[rg][3], ahi_b + ao);
            LDSM_X4(al[rg][0],al[rg][1],al[rg][2],al[rg][3], alo_b + ao);
        }
        #pragma unroll
        for (int nt = 0; nt < 4; nt++) {
            const int nb2 = nh * 32 + nt * 8;
            const uint32_t bofs =
                (uint32_t)((16 * ksw + brow8 + bmat * 8) * KPROW + nb2) * 2;
            uint32_t bh0,bh1, bl0,bl1;
            LDSM_X2T(bh0,bh1, vhi_b + bofs);
            LDSM_X2T(bl0,bl1, vlo_b + bofs);
            #pragma unroll
            for (int rg = 0; rg < 2; rg++) {
                MMA_BF16(d0[rg][nt],d1[rg][nt],d2[rg][nt],d3[rg][nt],
                         ah[rg][0],ah[rg][1],ah[rg][2],ah[rg][3], bl0,bl1);
                MMA_BF16(d0[rg][nt],d1[rg][nt],d2[rg][nt],d3[rg][nt],
                         al[rg][0],al[rg][1],al[rg][2],al[rg][3], bh0,bh1);
                MMA_BF16(d0[rg][nt],d1[rg][nt],d2[rg][nt],d3[rg][nt],
                         ah[rg][0],ah[rg][1],ah[rg][2],ah[rg][3], bh0,bh1);
            }
        }
        if (t < LDIM / KT - 1)
            convert_tile(pf, kbuf_hi[(t + 1) & 1], kbuf_lo[(t + 1) & 1], tid);
        __syncthreads();
    }

    // cross-warp reduction: 8 k-slice partials per n-half, via sc region
    float* red = (float*)(smem + OFF_SC);   // 16 warps * 32 rows * 32 cols fp32 = 64KB
    #pragma unroll
    for (int rg = 0; rg < 2; rg++)
        #pragma unroll
        for (int nt = 0; nt < 4; nt++) {
            const int nl = nt * 8 + 2 * tg;
            float* rp = red + w * 1024 + (rg * 16 + gr) * 32 + nl;
            *(float2*)rp            = make_float2(d0[rg][nt], d1[rg][nt]);
            *(float2*)(rp + 8 * 32) = make_float2(d2[rg][nt], d3[rg][nt]);
        }
    __syncthreads();
    {
        const int o  = tid * 4;          // 0..2044
        const int m  = o >> 6;           // 0..31
        const int n  = o & 63;
        const int wb = (n >> 5) * 8;
        const int nl = n & 31;
        float4 sum = make_float4(0.f, 0.f, 0.f, 0.f);
        #pragma unroll
        for (int j = 0; j < 8; j++) {
            float4 p = *(float4*)(red + (wb + j) * 1024 + m * 32 + nl);
            sum.x += p.x; sum.y += p.y; sum.z += p.z; sum.w += p.w;
        }
        *(float4*)(outg + ((size_t)b * LDIM + q_row0 + m) * DDIM + n) = sum;
    }
}

extern "C" void kernel_launch(void* const* d_in, const int* in_sizes, int n_in,
                              void* d_out, int out_size)
{
    const float* q    = (const float*)d_in[0];
    const float* k    = (const float*)d_in[1];
    const float* v    = (const float*)d_in[2];
    const int*   mask = (const int*)d_in[3];

    float* out  = (float*)d_out;                                // [B, Lq, D]
    float* attn = (float*)d_out + (size_t)BDIM * LDIM * DDIM;   // [B, Lq, Lk]

    cudaFuncSetAttribute(sparse_attn_kernel,
                         cudaFuncAttributeMaxDynamicSharedMemorySize,
                         SMEM_BYTES);

    dim3 grid(LDIM / TQ, BDIM);   // (32, 64)
    dim3 block(NTHR);
    sparse_attn_kernel<<<grid, block, SMEM_BYTES>>>(q, k, v, mask, out, attn);
}

// round 14
// speedup vs baseline: 12.8057x; 1.1350x over previous
#include <cuda_runtime.h>
#include <cuda_bf16.h>
#include <math.h>
#include <stdint.h>

// Problem constants: B=64, Lq=Lk=1024, D=64
#define BDIM   64
#define LDIM   1024
#define DDIM   64
#define TQ     32          // q rows per CTA
#define KT     128         // k/v rows per smem tile
#define NTHR   512
#define SCROW  1036        // fp32 score smem stride (floats)
#define APROW  1032        // attn bf16 plane stride (bf16 elems)
#define KPROW  72          // k/v bf16 plane stride (bf16) -> 144B rows
#define QPROW  72
#define TENS_SZ (BDIM * LDIM * DDIM)   // 4194304 elems

// smem byte layout:
//  [0)      q_hi 32x72 bf16 (4608) | q_lo (4608)                      -> 9216
//  [9216)   kv buf0: hi 128x72 (18432) | lo (18432)                   -> 46080
//  [46080)  kv buf1: hi | lo                                          -> 82944
//  [82944)  sc fp32 32x1036 (132608)
//           aliases: attn bf16 hi/lo planes + GEMM2 reduction scratch
#define OFF_QHI 0
#define OFF_QLO 4608
#define OFF_K0  9216
#define KBUF_SZ 36864
#define OFF_SC  82944
#define SMEM_BYTES 215552

// global bf16 hi/lo planes (prepass output)
__device__ __nv_bfloat16 g_qhi[TENS_SZ], g_qlo[TENS_SZ];
__device__ __nv_bfloat16 g_khi[TENS_SZ], g_klo[TENS_SZ];
__device__ __nv_bfloat16 g_vhi[TENS_SZ], g_vlo[TENS_SZ];

__device__ __forceinline__ uint32_t sptr(const void* p) {
    return (uint32_t)__cvta_generic_to_shared(p);
}
__device__ __forceinline__ void bsplit(float x, uint16_t& h, uint16_t& l) {
    __nv_bfloat16 bh = __float2bfloat16(x);
    float r = x - __bfloat162float(bh);
    __nv_bfloat16 bl = __float2bfloat16(r);
    h = __bfloat16_as_ushort(bh);
    l = __bfloat16_as_ushort(bl);
}

#define LDSM_X4(r0,r1,r2,r3, a)                                                  \
    asm volatile("ldmatrix.sync.aligned.m8n8.x4.shared.b16 {%0,%1,%2,%3}, [%4];" \
        : "=r"(r0), "=r"(r1), "=r"(r2), "=r"(r3) : "r"(a))
#define LDSM_X2(r0,r1, a)                                                        \
    asm volatile("ldmatrix.sync.aligned.m8n8.x2.shared.b16 {%0,%1}, [%2];"       \
        : "=r"(r0), "=r"(r1) : "r"(a))
#define LDSM_X2T(r0,r1, a)                                                       \
    asm volatile("ldmatrix.sync.aligned.m8n8.x2.trans.shared.b16 {%0,%1}, [%2];" \
        : "=r"(r0), "=r"(r1) : "r"(a))
#define MMA_BF16(c0,c1,c2,c3, a0,a1,a2,a3, b0,b1)                                \
    asm volatile("mma.sync.aligned.m16n8k16.row.col.f32.bf16.bf16.f32 "          \
        "{%0,%1,%2,%3}, {%4,%5,%6,%7}, {%8,%9}, {%0,%1,%2,%3};"                  \
        : "+f"(c0), "+f"(c1), "+f"(c2), "+f"(c3)                                 \
        : "r"(a0), "r"(a1), "r"(a2), "r"(a3), "r"(b0), "r"(b1))

__device__ __forceinline__ void cpa16(uint32_t dst, const void* src) {
    asm volatile("cp.async.ca.shared.global [%0], [%1], 16;" :: "r"(dst), "l"(src));
}
#define CP_COMMIT() asm volatile("cp.async.commit_group;" ::: "memory")
#define CP_WAIT0()  asm volatile("cp.async.wait_group 0;"  ::: "memory")

// ============================ prepass: fp32 -> bf16 hi/lo planes ============================
__global__ __launch_bounds__(256)
void split_kernel(const float* __restrict__ q,
                  const float* __restrict__ k,
                  const float* __restrict__ v)
{
    const size_t i = ((size_t)blockIdx.x * 256 + threadIdx.x) * 4;
    const int which = blockIdx.y;
    const float* src = (which == 0) ? q : (which == 1) ? k : v;
    __nv_bfloat16* dh = (which == 0) ? g_qhi : (which == 1) ? g_khi : g_vhi;
    __nv_bfloat16* dl = (which == 0) ? g_qlo : (which == 1) ? g_klo : g_vlo;
    const float sc = (which == 0) ? 0.125f : 1.0f;

    float4 f = *(const float4*)(src + i);
    f.x *= sc; f.y *= sc; f.z *= sc; f.w *= sc;
    uint16_t h0,l0,h1,l1,h2,l2,h3,l3;
    bsplit(f.x, h0, l0); bsplit(f.y, h1, l1);
    bsplit(f.z, h2, l2); bsplit(f.w, h3, l3);
    *(uint2*)(dh + i) = make_uint2((uint32_t)h0 | ((uint32_t)h1 << 16),
                                   (uint32_t)h2 | ((uint32_t)h3 << 16));
    *(uint2*)(dl + i) = make_uint2((uint32_t)l0 | ((uint32_t)l1 << 16),
                                   (uint32_t)l2 | ((uint32_t)l3 << 16));
}

// issue one [128 x 64] bf16 hi/lo tile via cp.async (4 x 16B per thread)
__device__ __forceinline__ void issue_kv_tile(const __nv_bfloat16* __restrict__ ghi,
                                              const __nv_bfloat16* __restrict__ glo,
                                              int tile, uint32_t bhi, uint32_t blo, int tid)
{
    #pragma unroll
    for (int j = 0; j < 2; j++) {
        const int g   = tid + j * 512;
        const int row = g >> 3;
        const int c8  = (g & 7) * 8;
        const size_t off = (size_t)(tile * KT + row) * DDIM + c8;
        const uint32_t d = (uint32_t)((row * KPROW + c8) * 2);
        cpa16(bhi + d, ghi + off);
        cpa16(blo + d, glo + off);
    }
}

// ============================ main kernel ============================
__global__ __launch_bounds__(NTHR, 1)
void sparse_attn_kernel(const int* __restrict__ maskg,
                        float* __restrict__ outg,
                        float* __restrict__ attng)
{
    extern __shared__ char smem[];
    uint16_t* q_hi = (uint16_t*)(smem + OFF_QHI);
    uint16_t* q_lo = (uint16_t*)(smem + OFF_QLO);
    float*    sc_s = (float*)   (smem + OFF_SC);
    uint16_t* a_hi = (uint16_t*)(smem + OFF_SC);    // attn hi plane (aliases sc)
    uint16_t* a_lo = a_hi + TQ * APROW;             // attn lo plane

    const uint32_t kb_hi[2] = { sptr(smem + OFF_K0),
                                sptr(smem + OFF_K0 + KBUF_SZ) };
    const uint32_t kb_lo[2] = { sptr(smem + OFF_K0 + KBUF_SZ/2),
                                sptr(smem + OFF_K0 + KBUF_SZ + KBUF_SZ/2) };

    const int qt   = blockIdx.x;            // 0..31
    const int b    = blockIdx.y;            // 0..63
    const int tid  = threadIdx.x;
    const int w    = tid >> 5;              // warp 0..15
    const int lane = tid & 31;
    const int gr   = lane >> 2;             // 0..7
    const int tg   = lane & 3;              // 0..3

    const int q_row0 = qt * TQ;
    const __nv_bfloat16* qhi_g = g_qhi + ((size_t)b * LDIM + q_row0) * DDIM;
    const __nv_bfloat16* qlo_g = g_qlo + ((size_t)b * LDIM + q_row0) * DDIM;
    const __nv_bfloat16* khi_g = g_khi + (size_t)b * LDIM * DDIM;
    const __nv_bfloat16* klo_g = g_klo + (size_t)b * LDIM * DDIM;
    const __nv_bfloat16* vhi_g = g_vhi + (size_t)b * LDIM * DDIM;
    const __nv_bfloat16* vlo_g = g_vlo + (size_t)b * LDIM * DDIM;

    // ldmatrix lane addressing
    const int g4      = lane >> 3;
    const int arow    = (lane & 7) | ((g4 & 1) << 3);   // A row within 16
    const int acolofs = (g4 >> 1) << 3;                 // A +0/+8 k-offset
    const int li      = lane & 15;
    const int brow8   = li & 7;
    const int bmat    = li >> 3;

    // ---- prologue: cp.async q planes + k tile 0 (one group) ----
    {
        const int pl  = tid >> 8;           // 0=hi 1=lo
        const int g   = tid & 255;
        const int row = g >> 3;
        const int c8  = (g & 7) * 8;
        const size_t off = (size_t)row * DDIM + c8;
        const __nv_bfloat16* src = (pl ? qlo_g : qhi_g) + off;
        const uint32_t dst = (pl ? sptr(q_lo) : sptr(q_hi)) + (uint32_t)((row * QPROW + c8) * 2);
        cpa16(dst, src);
    }
    issue_kv_tile(khi_g, klo_g, 0, kb_hi[0], kb_lo[0], tid);
    CP_COMMIT();
    CP_WAIT0();
    __syncthreads();   // q planes + k buf0 ready

    // ---- hoist q fragments into registers ----
    const uint32_t qhi_b = sptr(q_hi), qlo_b = sptr(q_lo);
    uint32_t qa_h[2][4][4], qa_l[2][4][4];
    #pragma unroll
    for (int rg = 0; rg < 2; rg++)
        #pragma unroll
        for (int kc = 0; kc < 4; kc++) {
            const uint32_t ao =
                (uint32_t)((rg * 16 + arow) * QPROW + kc * 16 + acolofs) * 2;
            LDSM_X4(qa_h[rg][kc][0], qa_h[rg][kc][1], qa_h[rg][kc][2], qa_h[rg][kc][3],
                    qhi_b + ao);
            LDSM_X4(qa_l[rg][kc][0], qa_l[rg][kc][1], qa_l[rg][kc][2], qa_l[rg][kc][3],
                    qlo_b + ao);
        }

    // ==================== GEMM1: scores = (q/8) . k^T  (bf16x3, cp.async pipeline) ====================
    const int nb = 8 * w;
    for (int t = 0; t < LDIM / KT; t++) {
        CP_WAIT0();        // tile t arrived (prologue / previous iteration)
        __syncthreads();   // visible to all; previous tile's reads complete
        if (t < LDIM / KT - 1) {
            issue_kv_tile(khi_g, klo_g, t + 1, kb_hi[(t+1)&1], kb_lo[(t+1)&1], tid);
            CP_COMMIT();
        }

        const uint32_t khi_b = kb_hi[t & 1];
        const uint32_t klo_b = kb_lo[t & 1];
        float c0[2] = {0.f,0.f}, c1[2] = {0.f,0.f}, c2[2] = {0.f,0.f}, c3[2] = {0.f,0.f};
        #pragma unroll
        for (int kc = 0; kc < 4; kc++) {
            uint32_t bh0,bh1, bl0,bl1;
            const uint32_t bofs = (uint32_t)((nb + brow8) * KPROW + kc * 16 + bmat * 8) * 2;
            LDSM_X2(bh0,bh1, khi_b + bofs);
            LDSM_X2(bl0,bl1, klo_b + bofs);
            #pragma unroll
            for (int rg = 0; rg < 2; rg++) {
                MMA_BF16(c0[rg],c1[rg],c2[rg],c3[rg],
                         qa_h[rg][kc][0],qa_h[rg][kc][1],qa_h[rg][kc][2],qa_h[rg][kc][3],
                         bl0,bl1);
                MMA_BF16(c0[rg],c1[rg],c2[rg],c3[rg],
                         qa_l[rg][kc][0],qa_l[rg][kc][1],qa_l[rg][kc][2],qa_l[rg][kc][3],
                         bh0,bh1);
                MMA_BF16(c0[rg],c1[rg],c2[rg],c3[rg],
                         qa_h[rg][kc][0],qa_h[rg][kc][1],qa_h[rg][kc][2],qa_h[rg][kc][3],
                         bh0,bh1);
            }
        }
        #pragma unroll
        for (int rg = 0; rg < 2; rg++) {
            float* sp = sc_s + (rg * 16 + gr) * SCROW + t * KT + nb + 2 * tg;
            *(float2*)sp               = make_float2(c0[rg], c1[rg]);
            *(float2*)(sp + 8 * SCROW) = make_float2(c2[rg], c3[rg]);
        }
    }

    // issue v tile 0 now — latency hides behind sparsemax
    issue_kv_tile(vhi_g, vlo_g, 0, kb_hi[0], kb_lo[0], tid);
    CP_COMMIT();
    __syncthreads();   // all score stores visible

    // ============ mask + sparsemax (Michelot; warp handles 2 rows sequentially) ============
    float taus[2];
    float az[2][32];
    #pragma unroll
    for (int rr = 0; rr < 2; rr++) {
        const int row  = w * 2 + rr;
        const int grow = q_row0 + row;
        float* z = az[rr];
        {
            const int4* m4 = (const int4*)(maskg + ((size_t)b * LDIM + grow) * LDIM);
            #pragma unroll
            for (int jj = 0; jj < 8; jj++) {
                int col = lane * 4 + 128 * jj;
                int4   mb = m4[col >> 2];
                float4 s  = *(float4*)(sc_s + row * SCROW + col);
                z[jj*4+0] = mb.x ? -INFINITY : s.x;
                z[jj*4+1] = mb.y ? -INFINITY : s.y;
                z[jj*4+2] = mb.z ? -INFINITY : s.z;
                z[jj*4+3] = mb.w ? -INFINITY : s.w;
            }
        }
        float s = 0.0f; int c = 0;
        #pragma unroll
        for (int i = 0; i < 32; i++)
            if (z[i] > -INFINITY) { s += z[i]; c++; }
        #pragma unroll
        for (int o = 16; o >= 1; o >>= 1) {
            s += __shfl_xor_sync(0xffffffffu, s, o);
            c += __shfl_xor_sync(0xffffffffu, c, o);
        }
        float tau = (c > 0) ? (s - 1.0f) / (float)c : INFINITY;
        int prev = c;
        for (int it = 0; it < 64; it++) {
            float s2 = 0.0f; int c2 = 0;
            #pragma unroll
            for (int i = 0; i < 32; i++)
                if (z[i] > tau) { s2 += z[i]; c2++; }
            #pragma unroll
            for (int o = 16; o >= 1; o >>= 1) {
                s2 += __shfl_xor_sync(0xffffffffu, s2, o);
                c2 += __shfl_xor_sync(0xffffffffu, c2, o);
            }
            bool done = (c2 == prev) || (c2 == 0);
            prev = c2;
            if (c2 > 0) tau = (s2 - 1.0f) / (float)c2;
            if (done) break;   // warp-uniform
        }
        taus[rr] = tau;
    }
    __syncthreads();   // all score reads done before attn planes overwrite region

    // attn = max(z - tau, 0): fp32 -> global; bf16 hi/lo -> planes
    #pragma unroll
    for (int rr = 0; rr < 2; rr++) {
        const int row  = w * 2 + rr;
        const int grow = q_row0 + row;
        const float tau = taus[rr];
        float* z = az[rr];
        float* attn_row = attng + ((size_t)b * LDIM + grow) * LDIM;
        #pragma unroll
        for (int jj = 0; jj < 8; jj++) {
            int col = lane * 4 + 128 * jj;
            float a0 = fmaxf(z[jj*4+0] - tau, 0.0f);
            float a1 = fmaxf(z[jj*4+1] - tau, 0.0f);
            float a2 = fmaxf(z[jj*4+2] - tau, 0.0f);
            float a3 = fmaxf(z[jj*4+3] - tau, 0.0f);
            *(float4*)(attn_row + col) = make_float4(a0, a1, a2, a3);
            uint16_t h0,l0,h1,l1,h2,l2,h3,l3;
            bsplit(a0,h0,l0); bsplit(a1,h1,l1); bsplit(a2,h2,l2); bsplit(a3,h3,l3);
            *(uint2*)(a_hi + row * APROW + col) =
                make_uint2((uint32_t)h0 | ((uint32_t)h1<<16), (uint32_t)h2 | ((uint32_t)h3<<16));
            *(uint2*)(a_lo + row * APROW + col) =
                make_uint2((uint32_t)l0 | ((uint32_t)l1<<16), (uint32_t)l2 | ((uint32_t)l3<<16));
        }
    }

    // ==================== GEMM2: out = attn . v  (bf16x3, cp.async pipeline) ====================
    const int ksw = w & 7;
    const int nh  = w >> 3;
    const uint32_t ahi_b = sptr(a_hi), alo_b = sptr(a_lo);
    float d0[2][4], d1[2][4], d2[2][4], d3[2][4];
    #pragma unroll
    for (int rg = 0; rg < 2; rg++)
        #pragma unroll
        for (int nt = 0; nt < 4; nt++) { d0[rg][nt]=d1[rg][nt]=d2[rg][nt]=d3[rg][nt]=0.f; }

    for (int t = 0; t < LDIM / KT; t++) {
        CP_WAIT0();        // v tile t arrived
        __syncthreads();   // t=0 also orders attn plane writes vs LDSM reads
        if (t < LDIM / KT - 1) {
            issue_kv_tile(vhi_g, vlo_g, t + 1, kb_hi[(t+1)&1], kb_lo[(t+1)&1], tid);
            CP_COMMIT();
        }

        const uint32_t vhi_b = kb_hi[t & 1];
        const uint32_t vlo_b = kb_lo[t & 1];
        const int ka = t * KT + 16 * ksw;
        uint32_t ah[2][4], al[2][4];
        #pragma unroll
        for (int rg = 0; rg < 2; rg++) {
            const uint32_t ao =
                (uint32_t)((rg * 16 + arow) * APROW + ka + acolofs) * 2;
            LDSM_X4(ah[rg][0],ah[rg][1],ah[rg][2],ah[rg][3], ahi_b + ao);
            LDSM_X4(al[rg][0],al[rg][1],al[rg][2],al[rg][3], alo_b + ao);
        }
        #pragma unroll
        for (int nt = 0; nt < 4; nt++) {
            const int nb2 = nh * 32 + nt * 8;
            const uint32_t bofs =
                (uint32_t)((16 * ksw + brow8 + bmat * 8) * KPROW + nb2) * 2;
            uint32_t bh0,bh1, bl0,bl1;
            LDSM_X2T(bh0,bh1, vhi_b + bofs);
            LDSM_X2T(bl0,bl1, vlo_b + bofs);
            #pragma unroll
            for (int rg = 0; rg < 2; rg++) {
                MMA_BF16(d0[rg][nt],d1[rg][nt],d2[rg][nt],d3[rg][nt],
                         ah[rg][0],ah[rg][1],ah[rg][2],ah[rg][3], bl0,bl1);
                MMA_BF16(d0[rg][nt],d1[rg][nt],d2[rg][nt],d3[rg][nt],
                         al[rg][0],al[rg][1],al[rg][2],al[rg][3], bh0,bh1);
                MMA_BF16(d0[rg][nt],d1[rg][nt],d2[rg][nt],d3[rg][nt],
                         ah[rg][0],ah[rg][1],ah[rg][2],ah[rg][3], bh0,bh1);
            }
        }
    }
    __syncthreads();   // attn/v plane reads done -> reduction may overwrite region

    // cross-warp reduction: 8 k-slice partials per n-half, via sc region
    float* red = (float*)(smem + OFF_SC);
    #pragma unroll
    for (int rg = 0; rg < 2; rg++)
        #pragma unroll
        for (int nt = 0; nt < 4; nt++) {
            const int nl = nt * 8 + 2 * tg;
            float* rp = red + w * 1024 + (rg * 16 + gr) * 32 + nl;
            *(float2*)rp            = make_float2(d0[rg][nt], d1[rg][nt]);
            *(float2*)(rp + 8 * 32) = make_float2(d2[rg][nt], d3[rg][nt]);
        }
    __syncthreads();
    {
        const int o  = tid * 4;
        const int m  = o >> 6;
        const int n  = o & 63;
        const int wb = (n >> 5) * 8;
        const int nl = n & 31;
        float4 sum = make_float4(0.f, 0.f, 0.f, 0.f);
        #pragma unroll
        for (int j = 0; j < 8; j++) {
            float4 p = *(float4*)(red + (wb + j) * 1024 + m * 32 + nl);
            sum.x += p.x; sum.y += p.y; sum.z += p.z; sum.w += p.w;
        }
        *(float4*)(outg + ((size_t)b * LDIM + q_row0 + m) * DDIM + n) = sum;
    }
}

extern "C" void kernel_launch(void* const* d_in, const int* in_sizes, int n_in,
                              void* d_out, int out_size)
{
    const float* q    = (const float*)d_in[0];
    const float* k    = (const float*)d_in[1];
    const float* v    = (const float*)d_in[2];
    const int*   mask = (const int*)d_in[3];

    float* out  = (float*)d_out;                                // [B, Lq, D]
    float* attn = (float*)d_out + (size_t)BDIM * LDIM * DDIM;   // [B, Lq, Lk]

    // prepass: fp32 -> bf16 hi/lo planes (once per call)
    dim3 pgrid(TENS_SZ / (256 * 4), 3);
    split_kernel<<<pgrid, 256>>>(q, k, v);

    cudaFuncSetAttribute(sparse_attn_kernel,
                         cudaFuncAttributeMaxDynamicSharedMemorySize,
                         SMEM_BYTES);
    dim3 grid(LDIM / TQ, BDIM);   // (32, 64)
    dim3 block(NTHR);
    sparse_attn_kernel<<<grid, block, SMEM_BYTES>>>(mask, out, attn);
}